// round 2
// baseline (speedup 1.0000x reference)
#include <cuda_runtime.h>
#include <cstdint>

#define DV 128
#define NSTEP 10
#define BSZ 4096
#define CNT0 20000
#define CNT1 2000
#define CNT2 15000
#define ROWS_TOT (CNT0 + CNT1 + CNT2)

typedef unsigned long long u64;

// Scratch (static __device__ arrays: allocation-guard safe)
__device__ __align__(16) float g_P[2 * ROWS_TOT * DV];     // 37.9 MB: precomputed x@Wih^T + biases
__device__ __align__(16) float g_agg[18 * BSZ * DV];       // 37.7 MB: RNN means per (l,set,nt)

static __device__ __forceinline__ u64 pack2(float x, float y){
  u64 r;
  asm("mov.b64 %0, {%1,%2};" : "=l"(r) : "r"(__float_as_uint(x)), "r"(__float_as_uint(y)));
  return r;
}
static __device__ __forceinline__ float2 unpack2(u64 v){
  unsigned lo, hi;
  asm("mov.b64 {%0,%1}, %2;" : "=r"(lo), "=r"(hi) : "l"(v));
  return make_float2(__uint_as_float(lo), __uint_as_float(hi));
}
// Packed dual-fp32 FMA (sm_103a FFMA2) — only reachable via PTX fma.rn.f32x2
static __device__ __forceinline__ void ffma2(u64 &d, u64 a, u64 b){
  asm("fma.rn.f32x2 %0, %1, %2, %0;" : "+l"(d) : "l"(a), "l"(b));
}
// tanh via EX2+RCP: abs error ~1e-7, saturates correctly at +/-inf
static __device__ __forceinline__ float tanh_fast(float x){
  float e = __expf(2.0f * x);
  return 1.0f - __fdividef(2.0f, e + 1.0f);
}

// ---------------------------------------------------------------------------
// Kernel 1: P[l][nt] = emb[nt] @ Wih[l,nt]^T + bih[l,nt] + bhh[l,nt]
// block: 512 threads, 128 rows x 128 cols tile. Wih transposed in smem.
// ---------------------------------------------------------------------------
__global__ void __launch_bounds__(512, 1) precompute_P_kernel(
    const float* __restrict__ emb0, const float* __restrict__ emb1, const float* __restrict__ emb2,
    const float* __restrict__ Wih, const float* __restrict__ bih, const float* __restrict__ bhh)
{
  extern __shared__ float sm[];
  float* Wsh = sm;               // [128][130]  W[k][j] (transposed, stride 130 keeps LDS.64 aligned + conflict-free)
  float* As  = sm + DV * 130;    // [128][33]
  const int tid  = threadIdx.x;
  const int comb = blockIdx.y;   // l*3 + nt
  const int nt   = comb % 3;
  const int l    = comb / 3;
  const int rows = (nt == 0) ? CNT0 : ((nt == 1) ? CNT1 : CNT2);
  const int row0 = blockIdx.x * 128;
  if (row0 >= rows) return;
  const float* emb = (nt == 0) ? emb0 : ((nt == 1) ? emb1 : emb2);
  const float* Wb  = Wih + (size_t)comb * DV * DV;

  for (int idx = tid; idx < DV * DV; idx += 512){
    int j = idx >> 7, k = idx & 127;
    Wsh[k * 130 + j] = Wb[idx];
  }
  __syncthreads();

  const int r0 = (tid >> 4) * 4;        // 4 consecutive rows
  const int jc = (tid & 15) * 2;        // column pairs at jc + 32*p  (conflict-free LDS.64)
  u64 acc[4][4] = {};

  for (int kc = 0; kc < 4; kc++){
    for (int idx = tid; idx < 128 * 32; idx += 512){
      int r = idx >> 5, k = idx & 31;
      int gr = row0 + r;
      As[r * 33 + k] = (gr < rows) ? emb[(size_t)gr * DV + kc * 32 + k] : 0.0f;
    }
    __syncthreads();
    #pragma unroll 4
    for (int k = 0; k < 32; k++){
      const float a0 = As[(r0 + 0) * 33 + k];
      const float a1 = As[(r0 + 1) * 33 + k];
      const float a2 = As[(r0 + 2) * 33 + k];
      const float a3 = As[(r0 + 3) * 33 + k];
      const u64 b0 = pack2(a0, a0), b1 = pack2(a1, a1), b2 = pack2(a2, a2), b3 = pack2(a3, a3);
      const float* wr = &Wsh[(kc * 32 + k) * 130 + jc];
      const u64 w0 = *(const u64*)(wr);
      const u64 w1 = *(const u64*)(wr + 32);
      const u64 w2 = *(const u64*)(wr + 64);
      const u64 w3 = *(const u64*)(wr + 96);
      ffma2(acc[0][0], b0, w0); ffma2(acc[0][1], b0, w1); ffma2(acc[0][2], b0, w2); ffma2(acc[0][3], b0, w3);
      ffma2(acc[1][0], b1, w0); ffma2(acc[1][1], b1, w1); ffma2(acc[1][2], b1, w2); ffma2(acc[1][3], b1, w3);
      ffma2(acc[2][0], b2, w0); ffma2(acc[2][1], b2, w1); ffma2(acc[2][2], b2, w2); ffma2(acc[2][3], b2, w3);
      ffma2(acc[3][0], b3, w0); ffma2(acc[3][1], b3, w1); ffma2(acc[3][2], b3, w2); ffma2(acc[3][3], b3, w3);
    }
    __syncthreads();
  }

  const float* bi = bih + (size_t)comb * DV;
  const float* bh = bhh + (size_t)comb * DV;
  const size_t Poff = (size_t)l * ROWS_TOT * DV
                    + (size_t)((nt == 0) ? 0 : ((nt == 1) ? CNT0 : (CNT0 + CNT1))) * DV;
  #pragma unroll
  for (int i = 0; i < 4; i++){
    int gr = row0 + r0 + i;
    if (gr < rows){
      float* outr = g_P + Poff + (size_t)gr * DV;
      #pragma unroll
      for (int p = 0; p < 4; p++){
        int j = jc + 32 * p;
        float2 a = unpack2(acc[i][p]);
        a.x += bi[j]     + bh[j];
        a.y += bi[j + 1] + bh[j + 1];
        *(float2*)(outr + j) = a;
      }
    }
  }
}

// ---------------------------------------------------------------------------
// Kernel 2: all 18 (layer,set,nt) RNN-mean aggregations.
// block = (combo, 128-row tile). Whh + double-buffered h in smem.
// acc initialized from gathered P rows -> p-load latency hidden under matmul.
// ---------------------------------------------------------------------------
__global__ void __launch_bounds__(512, 1) rnn_agg_kernel(
    const float* __restrict__ Whh,
    const int* __restrict__ c_ids, const int* __restrict__ pos_ids, const int* __restrict__ neg_ids,
    const int* __restrict__ n00, const int* __restrict__ n01, const int* __restrict__ n02,
    const int* __restrict__ n10, const int* __restrict__ n11, const int* __restrict__ n12)
{
  extern __shared__ float sm[];
  float* Wsh   = sm;                       // [128][130]
  float* hA    = sm + DV * 130;            // [128][132]  (stride 132 -> 16B-aligned float4 rows)
  float* hB    = hA + DV * 132;            // [128][132]
  int*   nidsh = (int*)(hB + DV * 132);    // [128][10]

  const int tid = threadIdx.x;
  const int y   = blockIdx.y;              // l*9 + set*3 + nt
  const int l   = y / 9;
  const int rem = y % 9;
  const int set = rem / 3;
  const int nt  = rem % 3;
  const int ntype = (set == 0) ? 0 : 1;
  const int* ids = (set == 0) ? c_ids : ((set == 1) ? pos_ids : neg_ids);
  const int nsel = ntype * 3 + nt;
  const int* ntab = (nsel == 0) ? n00 : (nsel == 1) ? n01 : (nsel == 2) ? n02
                  : (nsel == 3) ? n10 : (nsel == 4) ? n11 : n12;
  const float* Wb = Whh + (size_t)(l * 3 + nt) * DV * DV;
  const float* Pb = g_P + (size_t)l * ROWS_TOT * DV
                  + (size_t)((nt == 0) ? 0 : ((nt == 1) ? CNT0 : (CNT0 + CNT1))) * DV;
  const int row0 = blockIdx.x * 128;

  for (int idx = tid; idx < DV * DV; idx += 512){
    int j = idx >> 7, k = idx & 127;
    Wsh[k * 130 + j] = Wb[idx];
  }
  for (int idx = tid; idx < 128 * NSTEP; idx += 512){
    int r = idx / NSTEP, s = idx % NSTEP;
    nidsh[idx] = ntab[(size_t)ids[row0 + r] * NSTEP + s];
  }
  __syncthreads();

  const int r0 = (tid >> 4) * 4;
  const int jc = (tid & 15) * 2;
  float2 hsum[4][4];
  #pragma unroll
  for (int i = 0; i < 4; i++)
    #pragma unroll
    for (int p = 0; p < 4; p++) hsum[i][p] = make_float2(0.0f, 0.0f);

  for (int s = 0; s < NSTEP; s++){
    float* rd  = (s & 1) ? hA : hB;   // written at step s-1
    float* wr_ = (s & 1) ? hB : hA;   // written this step (== rd of s-1, reads drained at prior sync)

    // acc <- gathered P rows (issues LDGs early; latency hidden under matmul)
    u64 acc[4][4];
    int nv[4];
    #pragma unroll
    for (int i = 0; i < 4; i++) nv[i] = nidsh[(r0 + i) * NSTEP + s];
    #pragma unroll
    for (int i = 0; i < 4; i++){
      const float* prow = Pb + (size_t)nv[i] * DV;
      #pragma unroll
      for (int p = 0; p < 4; p++)
        acc[i][p] = *(const u64*)(prow + jc + 32 * p);
    }

    if (s > 0){
      #pragma unroll 2
      for (int k = 0; k < DV; k += 4){
        float4 h0 = *(const float4*)&rd[(r0 + 0) * 132 + k];
        float4 h1 = *(const float4*)&rd[(r0 + 1) * 132 + k];
        float4 h2 = *(const float4*)&rd[(r0 + 2) * 132 + k];
        float4 h3 = *(const float4*)&rd[(r0 + 3) * 132 + k];
        const float* hp0 = (const float*)&h0;
        const float* hp1 = (const float*)&h1;
        const float* hp2 = (const float*)&h2;
        const float* hp3 = (const float*)&h3;
        #pragma unroll
        for (int kk = 0; kk < 4; kk++){
          const float* wrow = &Wsh[(k + kk) * 130 + jc];
          const u64 w0 = *(const u64*)(wrow);
          const u64 w1 = *(const u64*)(wrow + 32);
          const u64 w2 = *(const u64*)(wrow + 64);
          const u64 w3 = *(const u64*)(wrow + 96);
          const u64 b0 = pack2(hp0[kk], hp0[kk]);
          const u64 b1 = pack2(hp1[kk], hp1[kk]);
          const u64 b2 = pack2(hp2[kk], hp2[kk]);
          const u64 b3 = pack2(hp3[kk], hp3[kk]);
          ffma2(acc[0][0], b0, w0); ffma2(acc[0][1], b0, w1); ffma2(acc[0][2], b0, w2); ffma2(acc[0][3], b0, w3);
          ffma2(acc[1][0], b1, w0); ffma2(acc[1][1], b1, w1); ffma2(acc[1][2], b1, w2); ffma2(acc[1][3], b1, w3);
          ffma2(acc[2][0], b2, w0); ffma2(acc[2][1], b2, w1); ffma2(acc[2][2], b2, w2); ffma2(acc[2][3], b2, w3);
          ffma2(acc[3][0], b3, w0); ffma2(acc[3][1], b3, w1); ffma2(acc[3][2], b3, w2); ffma2(acc[3][3], b3, w3);
        }
      }
    }

    #pragma unroll
    for (int i = 0; i < 4; i++){
      #pragma unroll
      for (int p = 0; p < 4; p++){
        float2 a = unpack2(acc[i][p]);
        float hx = tanh_fast(a.x);
        float hy = tanh_fast(a.y);
        hsum[i][p].x += hx; hsum[i][p].y += hy;
        *(float2*)&wr_[(r0 + i) * 132 + jc + 32 * p] = make_float2(hx, hy);
      }
    }
    __syncthreads();
  }

  float* ob = g_agg + ((size_t)y * BSZ + row0) * DV;
  const float inv = 1.0f / NSTEP;
  #pragma unroll
  for (int i = 0; i < 4; i++){
    #pragma unroll
    for (int p = 0; p < 4; p++)
      *(float2*)&ob[(r0 + i) * DV + jc + 32 * p] =
          make_float2(hsum[i][p].x * inv, hsum[i][p].y * inv);
  }
}

// ---------------------------------------------------------------------------
// Kernel 3: attention over [cur, agg0, agg1, agg2], 2 layers, leaky-relu.
// ---------------------------------------------------------------------------
static __device__ __forceinline__ float breduce128(float v, float* sh){
  #pragma unroll
  for (int o = 16; o > 0; o >>= 1) v += __shfl_xor_sync(0xffffffffu, v, o);
  if ((threadIdx.x & 31) == 0) sh[threadIdx.x >> 5] = v;
  __syncthreads();
  float r = sh[0] + sh[1] + sh[2] + sh[3];
  __syncthreads();
  return r;
}

__global__ void __launch_bounds__(128) attn_kernel(
    const float* __restrict__ emb0, const float* __restrict__ emb1,
    const int* __restrict__ c_ids, const int* __restrict__ pos_ids, const int* __restrict__ neg_ids,
    const float* __restrict__ attW, float* __restrict__ out)
{
  __shared__ float sh[4];
  const int b   = blockIdx.x;
  const int set = blockIdx.y;
  const int d   = threadIdx.x;
  const int ntype = (set == 0) ? 0 : 1;
  const int* ids = (set == 0) ? c_ids : ((set == 1) ? pos_ids : neg_ids);
  const float* emb = (ntype == 0) ? emb0 : emb1;
  const int id = ids[b];
  float cur = emb[(size_t)id * DV + d];

  #pragma unroll
  for (int l = 0; l < 2; l++){
    const float* aw = attW + (size_t)(l * 3 + ntype) * 2 * DV;
    float awc = aw[d];
    float awn = aw[DV + d];
    float st0 = g_agg[((size_t)(l * 9 + set * 3 + 0) * BSZ + b) * DV + d];
    float st1 = g_agg[((size_t)(l * 9 + set * 3 + 1) * BSZ + b) * DV + d];
    float st2 = g_agg[((size_t)(l * 9 + set * 3 + 2) * BSZ + b) * DV + d];
    float base = breduce128(cur * awc, sh);
    float s0 = base + breduce128(cur * awn, sh);
    float s1 = base + breduce128(st0 * awn, sh);
    float s2 = base + breduce128(st1 * awn, sh);
    float s3 = base + breduce128(st2 * awn, sh);
    float m = fmaxf(fmaxf(s0, s1), fmaxf(s2, s3));
    float e0 = expf(s0 - m), e1 = expf(s1 - m), e2 = expf(s2 - m), e3 = expf(s3 - m);
    float inv = 1.0f / (e0 + e1 + e2 + e3);
    float v = (e0 * cur + e1 * st0 + e2 * st1 + e3 * st2) * inv;
    cur = (v > 0.0f) ? v : 0.01f * v;
  }
  out[((size_t)set * BSZ + b) * DV + d] = cur;
}

// ---------------------------------------------------------------------------
extern "C" void kernel_launch(void* const* d_in, const int* in_sizes, int n_in,
                              void* d_out, int out_size)
{
  const int*   c_ids   = (const int*)d_in[0];
  const int*   pos_ids = (const int*)d_in[1];
  const int*   neg_ids = (const int*)d_in[2];
  const int*   n00 = (const int*)d_in[3];
  const int*   n01 = (const int*)d_in[4];
  const int*   n02 = (const int*)d_in[5];
  const int*   n10 = (const int*)d_in[6];
  const int*   n11 = (const int*)d_in[7];
  const int*   n12 = (const int*)d_in[8];
  // d_in[9..11] = neigh_s2_* (unused: triple sets are types 0 and 1 only)
  const float* emb0 = (const float*)d_in[12];
  const float* emb1 = (const float*)d_in[13];
  const float* emb2 = (const float*)d_in[14];
  const float* Wih  = (const float*)d_in[15];
  const float* Whh  = (const float*)d_in[16];
  const float* bih  = (const float*)d_in[17];
  const float* bhh  = (const float*)d_in[18];
  const float* attW = (const float*)d_in[19];

  const int smemP = (DV * 130 + 128 * 33) * (int)sizeof(float);                         // 83,456 B
  const int smemR = (DV * 130 + 2 * DV * 132) * (int)sizeof(float)
                  + 128 * NSTEP * (int)sizeof(int);                                     // 206,848 B
  cudaFuncSetAttribute(precompute_P_kernel, cudaFuncAttributeMaxDynamicSharedMemorySize, smemP);
  cudaFuncSetAttribute(rnn_agg_kernel,      cudaFuncAttributeMaxDynamicSharedMemorySize, smemR);

  precompute_P_kernel<<<dim3(157, 6), 512, smemP>>>(emb0, emb1, emb2, Wih, bih, bhh);
  rnn_agg_kernel<<<dim3(BSZ / 128, 18), 512, smemR>>>(Whh, c_ids, pos_ids, neg_ids,
                                                      n00, n01, n02, n10, n11, n12);
  attn_kernel<<<dim3(BSZ, 3), 128>>>(emb0, emb1, c_ids, pos_ids, neg_ids, attW, (float*)d_out);
}

// round 4
// speedup vs baseline: 1.4947x; 1.4947x over previous
#include <cuda_runtime.h>
#include <cstdint>

#define DV 128
#define NSTEP 10
#define BSZ 4096
#define CNT0 20000
#define CNT1 2000
#define CNT2 15000
#define ROWS_TOT (CNT0 + CNT1 + CNT2)

typedef unsigned long long u64;

__device__ __align__(16) float g_P[2 * ROWS_TOT * DV];     // precomputed x@Wih^T + bih + bhh
__device__ __align__(16) float g_agg[18 * BSZ * DV];       // RNN means per (l,set,nt)

static __device__ __forceinline__ float2 unpack2(u64 v){
  unsigned lo, hi;
  asm("mov.b64 {%0,%1}, %2;" : "=r"(lo), "=r"(hi) : "l"(v));
  return make_float2(__uint_as_float(lo), __uint_as_float(hi));
}
// Packed dual-fp32 FMA (sm_103 FFMA2) — only reachable via PTX fma.rn.f32x2
static __device__ __forceinline__ void ffma2(u64 &d, u64 a, u64 b){
  asm("fma.rn.f32x2 %0, %1, %2, %0;" : "+l"(d) : "l"(a), "l"(b));
}
// tanh via EX2+RCP: abs err ~1e-7 (empirically amplification ~1x -> out rel_err ~1.6e-7)
static __device__ __forceinline__ float tanh_fast(float x){
  float e = __expf(2.0f * x);
  return 1.0f - __fdividef(2.0f, e + 1.0f);
}

// ---------------------------------------------------------------------------
// Kernel 1: P[l][nt] = emb[nt] @ Wih[l,nt]^T + bih + bhh (SIMT f32x2).
// Full A tile upfront, stored as DUPLICATED pairs -> (a,a) = one LDS.64.
// ---------------------------------------------------------------------------
__global__ void __launch_bounds__(512, 1) precompute_P_kernel(
    const float* __restrict__ emb0, const float* __restrict__ emb1, const float* __restrict__ emb2,
    const float* __restrict__ Wih, const float* __restrict__ bih, const float* __restrict__ bhh)
{
  extern __shared__ float sm[];
  float* Wsh = sm;               // [128][130]  W[k][j] transposed
  float* Asd = sm + DV * 130;    // [128][264]  duplicated A pairs
  const int tid  = threadIdx.x;
  const int comb = blockIdx.y;   // l*3 + nt
  const int nt   = comb % 3;
  const int l    = comb / 3;
  const int rows = (nt == 0) ? CNT0 : ((nt == 1) ? CNT1 : CNT2);
  const int row0 = blockIdx.x * 128;
  if (row0 >= rows) return;
  const float* emb = (nt == 0) ? emb0 : ((nt == 1) ? emb1 : emb2);
  const float* Wb  = Wih + (size_t)comb * DV * DV;

  for (int idx = tid; idx < DV * DV; idx += 512){
    int j = idx >> 7, k = idx & 127;
    Wsh[k * 130 + j] = Wb[idx];
  }
  for (int idx = tid; idx < 128 * 32; idx += 512){
    int r = idx >> 5, q = idx & 31;
    int gr = row0 + r;
    float4 v = make_float4(0.f, 0.f, 0.f, 0.f);
    if (gr < rows) v = *(const float4*)(emb + (size_t)gr * DV + 4 * q);
    float* dst = &Asd[r * 264 + 8 * q];
    *(float4*)(dst)     = make_float4(v.x, v.x, v.y, v.y);
    *(float4*)(dst + 4) = make_float4(v.z, v.z, v.w, v.w);
  }
  __syncthreads();

  const int r0 = (tid >> 4) * 4;
  const int jc = (tid & 15) * 2;
  u64 acc[4][4] = {};

  #pragma unroll 4
  for (int k = 0; k < DV; k++){
    const u64 b0 = *(const u64*)&Asd[(r0 + 0) * 264 + 2 * k];
    const u64 b1 = *(const u64*)&Asd[(r0 + 1) * 264 + 2 * k];
    const u64 b2 = *(const u64*)&Asd[(r0 + 2) * 264 + 2 * k];
    const u64 b3 = *(const u64*)&Asd[(r0 + 3) * 264 + 2 * k];
    const float* wr = &Wsh[k * 130 + jc];
    const u64 w0 = *(const u64*)(wr);
    const u64 w1 = *(const u64*)(wr + 32);
    const u64 w2 = *(const u64*)(wr + 64);
    const u64 w3 = *(const u64*)(wr + 96);
    ffma2(acc[0][0], b0, w0); ffma2(acc[0][1], b0, w1); ffma2(acc[0][2], b0, w2); ffma2(acc[0][3], b0, w3);
    ffma2(acc[1][0], b1, w0); ffma2(acc[1][1], b1, w1); ffma2(acc[1][2], b1, w2); ffma2(acc[1][3], b1, w3);
    ffma2(acc[2][0], b2, w0); ffma2(acc[2][1], b2, w1); ffma2(acc[2][2], b2, w2); ffma2(acc[2][3], b2, w3);
    ffma2(acc[3][0], b3, w0); ffma2(acc[3][1], b3, w1); ffma2(acc[3][2], b3, w2); ffma2(acc[3][3], b3, w3);
  }

  const float* bi = bih + (size_t)comb * DV;
  const float* bh = bhh + (size_t)comb * DV;
  const size_t Poff = (size_t)l * ROWS_TOT * DV
                    + (size_t)((nt == 0) ? 0 : ((nt == 1) ? CNT0 : (CNT0 + CNT1))) * DV;
  #pragma unroll
  for (int i = 0; i < 4; i++){
    int gr = row0 + r0 + i;
    if (gr < rows){
      float* outr = g_P + Poff + (size_t)gr * DV;
      #pragma unroll
      for (int p = 0; p < 4; p++){
        int j = jc + 32 * p;
        float2 a = unpack2(acc[i][p]);
        a.x += bi[j]     + bh[j];
        a.y += bi[j + 1] + bh[j + 1];
        *(float2*)(outr + j) = a;
      }
    }
  }
}

// ---------------------------------------------------------------------------
// Kernel 2: 18 (layer,set,nt) RNN-mean aggregations, SIMT f32x2.
// - h kept as DUPLICATED pairs in smem (broadcast operand = one LDS.64,
//   zero pack MOVs in the hot loop).
// - P gather prefetched into registers at step start, consumed ~16k cyc
//   later in the tanh epilogue (L2 latency fully hidden).
// - single h buffer, read/write phases separated by 2 bar.sync per step.
// ---------------------------------------------------------------------------
__global__ void __launch_bounds__(512, 1) rnn_agg_kernel(
    const float* __restrict__ Whh,
    const int* __restrict__ c_ids, const int* __restrict__ pos_ids, const int* __restrict__ neg_ids,
    const int* __restrict__ n00, const int* __restrict__ n01, const int* __restrict__ n02,
    const int* __restrict__ n10, const int* __restrict__ n11, const int* __restrict__ n12)
{
  extern __shared__ float sm[];
  float* Wsh   = sm;                       // [128][130]  W[k][j] transposed
  float* Hd    = sm + DV * 130;            // [128][264]  duplicated h pairs
  int*   nidsh = (int*)(Hd + DV * 264);    // [128][10]

  const int tid = threadIdx.x;
  const int y   = blockIdx.y;              // l*9 + set*3 + nt
  const int l   = y / 9;
  const int rem = y % 9;
  const int set = rem / 3;
  const int nt  = rem % 3;
  const int ntype = (set == 0) ? 0 : 1;
  const int* ids = (set == 0) ? c_ids : ((set == 1) ? pos_ids : neg_ids);
  const int nsel = ntype * 3 + nt;
  const int* ntab = (nsel == 0) ? n00 : (nsel == 1) ? n01 : (nsel == 2) ? n02
                  : (nsel == 3) ? n10 : (nsel == 4) ? n11 : n12;
  const float* Wb = Whh + (size_t)(l * 3 + nt) * DV * DV;
  const float* Pb = g_P + (size_t)l * ROWS_TOT * DV
                  + (size_t)((nt == 0) ? 0 : ((nt == 1) ? CNT0 : (CNT0 + CNT1))) * DV;
  const int row0 = blockIdx.x * 128;

  for (int idx = tid; idx < DV * DV; idx += 512){
    int j = idx >> 7, k = idx & 127;
    Wsh[k * 130 + j] = Wb[idx];
  }
  for (int idx = tid; idx < 128 * NSTEP; idx += 512){
    int r = idx / NSTEP, s = idx % NSTEP;
    nidsh[idx] = ntab[(size_t)ids[row0 + r] * NSTEP + s];
  }
  __syncthreads();

  const int r0 = (tid >> 4) * 4;
  const int jc = (tid & 15) * 2;
  float2 hsum[4][4];
  #pragma unroll
  for (int i = 0; i < 4; i++)
    #pragma unroll
    for (int p = 0; p < 4; p++) hsum[i][p] = make_float2(0.0f, 0.0f);

  for (int s = 0; s < NSTEP; s++){
    // prefetch P rows for THIS step into registers (consumed after the matmul)
    u64 Pr[4][4];
    #pragma unroll
    for (int i = 0; i < 4; i++){
      const int nv = nidsh[(r0 + i) * NSTEP + s];
      const float* prow = Pb + (size_t)nv * DV;
      #pragma unroll
      for (int p = 0; p < 4; p++)
        Pr[i][p] = *(const u64*)(prow + jc + 32 * p);
    }

    u64 acc[4][4] = {};
    if (s > 0){
      #pragma unroll 4
      for (int k = 0; k < DV; k++){
        const u64 b0 = *(const u64*)&Hd[(r0 + 0) * 264 + 2 * k];
        const u64 b1 = *(const u64*)&Hd[(r0 + 1) * 264 + 2 * k];
        const u64 b2 = *(const u64*)&Hd[(r0 + 2) * 264 + 2 * k];
        const u64 b3 = *(const u64*)&Hd[(r0 + 3) * 264 + 2 * k];
        const float* wr = &Wsh[k * 130 + jc];
        const u64 w0 = *(const u64*)(wr);
        const u64 w1 = *(const u64*)(wr + 32);
        const u64 w2 = *(const u64*)(wr + 64);
        const u64 w3 = *(const u64*)(wr + 96);
        ffma2(acc[0][0], b0, w0); ffma2(acc[0][1], b0, w1); ffma2(acc[0][2], b0, w2); ffma2(acc[0][3], b0, w3);
        ffma2(acc[1][0], b1, w0); ffma2(acc[1][1], b1, w1); ffma2(acc[1][2], b1, w2); ffma2(acc[1][3], b1, w3);
        ffma2(acc[2][0], b2, w0); ffma2(acc[2][1], b2, w1); ffma2(acc[2][2], b2, w2); ffma2(acc[2][3], b2, w3);
        ffma2(acc[3][0], b3, w0); ffma2(acc[3][1], b3, w1); ffma2(acc[3][2], b3, w2); ffma2(acc[3][3], b3, w3);
      }
    }
    __syncthreads();   // all reads of h_{s-1} done before overwrite

    #pragma unroll
    for (int i = 0; i < 4; i++){
      #pragma unroll
      for (int p = 0; p < 4; p++){
        float2 a = unpack2(acc[i][p]);
        float2 pv = unpack2(Pr[i][p]);
        float hx = tanh_fast(a.x + pv.x);
        float hy = tanh_fast(a.y + pv.y);
        hsum[i][p].x += hx; hsum[i][p].y += hy;
        // duplicated pair write: {hx,hx,hy,hy} = one STS.128
        *(float4*)&Hd[(r0 + i) * 264 + 2 * (jc + 32 * p)] = make_float4(hx, hx, hy, hy);
      }
    }
    __syncthreads();   // h_s visible before next matmul
  }

  float* ob = g_agg + ((size_t)y * BSZ + row0) * DV;
  const float inv = 1.0f / NSTEP;
  #pragma unroll
  for (int i = 0; i < 4; i++){
    #pragma unroll
    for (int p = 0; p < 4; p++)
      *(float2*)&ob[(r0 + i) * DV + jc + 32 * p] =
          make_float2(hsum[i][p].x * inv, hsum[i][p].y * inv);
  }
}

// ---------------------------------------------------------------------------
// Kernel 3: attention over [cur, agg0, agg1, agg2], 2 layers, leaky-relu.
// ---------------------------------------------------------------------------
static __device__ __forceinline__ float breduce128(float v, float* sh){
  #pragma unroll
  for (int o = 16; o > 0; o >>= 1) v += __shfl_xor_sync(0xffffffffu, v, o);
  if ((threadIdx.x & 31) == 0) sh[threadIdx.x >> 5] = v;
  __syncthreads();
  float r = sh[0] + sh[1] + sh[2] + sh[3];
  __syncthreads();
  return r;
}

__global__ void __launch_bounds__(128) attn_kernel(
    const float* __restrict__ emb0, const float* __restrict__ emb1,
    const int* __restrict__ c_ids, const int* __restrict__ pos_ids, const int* __restrict__ neg_ids,
    const float* __restrict__ attW, float* __restrict__ out)
{
  __shared__ float sh[4];
  const int b   = blockIdx.x;
  const int set = blockIdx.y;
  const int d   = threadIdx.x;
  const int ntype = (set == 0) ? 0 : 1;
  const int* ids = (set == 0) ? c_ids : ((set == 1) ? pos_ids : neg_ids);
  const float* emb = (ntype == 0) ? emb0 : emb1;
  const int id = ids[b];
  float cur = emb[(size_t)id * DV + d];

  #pragma unroll
  for (int l = 0; l < 2; l++){
    const float* aw = attW + (size_t)(l * 3 + ntype) * 2 * DV;
    float awc = aw[d];
    float awn = aw[DV + d];
    float st0 = g_agg[((size_t)(l * 9 + set * 3 + 0) * BSZ + b) * DV + d];
    float st1 = g_agg[((size_t)(l * 9 + set * 3 + 1) * BSZ + b) * DV + d];
    float st2 = g_agg[((size_t)(l * 9 + set * 3 + 2) * BSZ + b) * DV + d];
    float base = breduce128(cur * awc, sh);
    float s0 = base + breduce128(cur * awn, sh);
    float s1 = base + breduce128(st0 * awn, sh);
    float s2 = base + breduce128(st1 * awn, sh);
    float s3 = base + breduce128(st2 * awn, sh);
    float m = fmaxf(fmaxf(s0, s1), fmaxf(s2, s3));
    float e0 = expf(s0 - m), e1 = expf(s1 - m), e2 = expf(s2 - m), e3 = expf(s3 - m);
    float inv = 1.0f / (e0 + e1 + e2 + e3);
    float v = (e0 * cur + e1 * st0 + e2 * st1 + e3 * st2) * inv;
    cur = (v > 0.0f) ? v : 0.01f * v;
  }
  out[((size_t)set * BSZ + b) * DV + d] = cur;
}

// ---------------------------------------------------------------------------
extern "C" void kernel_launch(void* const* d_in, const int* in_sizes, int n_in,
                              void* d_out, int out_size)
{
  const int*   c_ids   = (const int*)d_in[0];
  const int*   pos_ids = (const int*)d_in[1];
  const int*   neg_ids = (const int*)d_in[2];
  const int*   n00 = (const int*)d_in[3];
  const int*   n01 = (const int*)d_in[4];
  const int*   n02 = (const int*)d_in[5];
  const int*   n10 = (const int*)d_in[6];
  const int*   n11 = (const int*)d_in[7];
  const int*   n12 = (const int*)d_in[8];
  // d_in[9..11] = neigh_s2_* (unused)
  const float* emb0 = (const float*)d_in[12];
  const float* emb1 = (const float*)d_in[13];
  const float* emb2 = (const float*)d_in[14];
  const float* Wih  = (const float*)d_in[15];
  const float* Whh  = (const float*)d_in[16];
  const float* bih  = (const float*)d_in[17];
  const float* bhh  = (const float*)d_in[18];
  const float* attW = (const float*)d_in[19];

  const int smemP = (DV * 130 + DV * 264) * (int)sizeof(float);                  // 201,728 B
  const int smemR = (DV * 130 + DV * 264) * (int)sizeof(float)
                  + 128 * NSTEP * (int)sizeof(int);                              // 206,848 B
  cudaFuncSetAttribute(precompute_P_kernel, cudaFuncAttributeMaxDynamicSharedMemorySize, smemP);
  cudaFuncSetAttribute(rnn_agg_kernel,      cudaFuncAttributeMaxDynamicSharedMemorySize, smemR);

  precompute_P_kernel<<<dim3(157, 6), 512, smemP>>>(emb0, emb1, emb2, Wih, bih, bhh);
  rnn_agg_kernel<<<dim3(BSZ / 128, 18), 512, smemR>>>(Whh, c_ids, pos_ids, neg_ids,
                                                      n00, n01, n02, n10, n11, n12);
  attn_kernel<<<dim3(BSZ, 3), 128>>>(emb0, emb1, c_ids, pos_ids, neg_ids, attW, (float*)d_out);
}

// round 5
// speedup vs baseline: 2.4753x; 1.6561x over previous
#include <cuda_runtime.h>
#include <cstdint>

#define DV 128
#define NSTEP 10
#define BSZ 4096
#define CNT0 20000
#define CNT1 2000
#define CNT2 15000
#define ROWS_TOT (CNT0 + CNT1 + CNT2)

typedef unsigned long long u64;

__device__ __align__(16) float g_P[2 * ROWS_TOT * DV];     // precomputed x@Wih^T + bih + bhh
__device__ __align__(16) float g_agg[18 * BSZ * DV];       // RNN means per (l,set,nt)

static __device__ __forceinline__ float2 unpack2(u64 v){
  unsigned lo, hi;
  asm("mov.b64 {%0,%1}, %2;" : "=r"(lo), "=r"(hi) : "l"(v));
  return make_float2(__uint_as_float(lo), __uint_as_float(hi));
}
static __device__ __forceinline__ void ffma2(u64 &d, u64 a, u64 b){
  asm("fma.rn.f32x2 %0, %1, %2, %0;" : "+l"(d) : "l"(a), "l"(b));
}
static __device__ __forceinline__ float tanh_fast(float x){
  float e = __expf(2.0f * x);
  return 1.0f - __fdividef(2.0f, e + 1.0f);
}
static __device__ __forceinline__ uint32_t tf32b(float v){
  uint32_t b;
  asm("cvt.rna.tf32.f32 %0, %1;" : "=r"(b) : "f"(v));
  return b;
}
// m16n8k8 tf32 HMMA: A row-major 16x8, B col-major 8x8 (k x n), C f32 16x8
static __device__ __forceinline__ void mma_tf32(float* c,
    uint32_t a0, uint32_t a1, uint32_t a2, uint32_t a3, uint32_t b0, uint32_t b1){
  asm volatile("mma.sync.aligned.m16n8k8.row.col.f32.tf32.tf32.f32 "
    "{%0,%1,%2,%3}, {%4,%5,%6,%7}, {%8,%9}, {%0,%1,%2,%3};"
    : "+f"(c[0]), "+f"(c[1]), "+f"(c[2]), "+f"(c[3])
    : "r"(a0), "r"(a1), "r"(a2), "r"(a3), "r"(b0), "r"(b1));
}

// ---------------------------------------------------------------------------
// Kernel 1: P[l][nt] = emb[nt] @ Wih[l,nt]^T + bih + bhh (SIMT f32x2).
// ---------------------------------------------------------------------------
__global__ void __launch_bounds__(512, 1) precompute_P_kernel(
    const float* __restrict__ emb0, const float* __restrict__ emb1, const float* __restrict__ emb2,
    const float* __restrict__ Wih, const float* __restrict__ bih, const float* __restrict__ bhh)
{
  extern __shared__ float sm[];
  float* Wsh = sm;               // [128][130]  W[k][j] transposed
  float* Asd = sm + DV * 130;    // [128][264]  duplicated A pairs
  const int tid  = threadIdx.x;
  const int comb = blockIdx.y;   // l*3 + nt
  const int nt   = comb % 3;
  const int l    = comb / 3;
  const int rows = (nt == 0) ? CNT0 : ((nt == 1) ? CNT1 : CNT2);
  const int row0 = blockIdx.x * 128;
  if (row0 >= rows) return;
  const float* emb = (nt == 0) ? emb0 : ((nt == 1) ? emb1 : emb2);
  const float* Wb  = Wih + (size_t)comb * DV * DV;

  for (int idx = tid; idx < DV * DV; idx += 512){
    int j = idx >> 7, k = idx & 127;
    Wsh[k * 130 + j] = Wb[idx];
  }
  for (int idx = tid; idx < 128 * 32; idx += 512){
    int r = idx >> 5, q = idx & 31;
    int gr = row0 + r;
    float4 v = make_float4(0.f, 0.f, 0.f, 0.f);
    if (gr < rows) v = *(const float4*)(emb + (size_t)gr * DV + 4 * q);
    float* dst = &Asd[r * 264 + 8 * q];
    *(float4*)(dst)     = make_float4(v.x, v.x, v.y, v.y);
    *(float4*)(dst + 4) = make_float4(v.z, v.z, v.w, v.w);
  }
  __syncthreads();

  const int r0 = (tid >> 4) * 4;
  const int jc = (tid & 15) * 2;
  u64 acc[4][4] = {};

  #pragma unroll 4
  for (int k = 0; k < DV; k++){
    const u64 b0 = *(const u64*)&Asd[(r0 + 0) * 264 + 2 * k];
    const u64 b1 = *(const u64*)&Asd[(r0 + 1) * 264 + 2 * k];
    const u64 b2 = *(const u64*)&Asd[(r0 + 2) * 264 + 2 * k];
    const u64 b3 = *(const u64*)&Asd[(r0 + 3) * 264 + 2 * k];
    const float* wr = &Wsh[k * 130 + jc];
    const u64 w0 = *(const u64*)(wr);
    const u64 w1 = *(const u64*)(wr + 32);
    const u64 w2 = *(const u64*)(wr + 64);
    const u64 w3 = *(const u64*)(wr + 96);
    ffma2(acc[0][0], b0, w0); ffma2(acc[0][1], b0, w1); ffma2(acc[0][2], b0, w2); ffma2(acc[0][3], b0, w3);
    ffma2(acc[1][0], b1, w0); ffma2(acc[1][1], b1, w1); ffma2(acc[1][2], b1, w2); ffma2(acc[1][3], b1, w3);
    ffma2(acc[2][0], b2, w0); ffma2(acc[2][1], b2, w1); ffma2(acc[2][2], b2, w2); ffma2(acc[2][3], b2, w3);
    ffma2(acc[3][0], b3, w0); ffma2(acc[3][1], b3, w1); ffma2(acc[3][2], b3, w2); ffma2(acc[3][3], b3, w3);
  }

  const float* bi = bih + (size_t)comb * DV;
  const float* bh = bhh + (size_t)comb * DV;
  const size_t Poff = (size_t)l * ROWS_TOT * DV
                    + (size_t)((nt == 0) ? 0 : ((nt == 1) ? CNT0 : (CNT0 + CNT1))) * DV;
  #pragma unroll
  for (int i = 0; i < 4; i++){
    int gr = row0 + r0 + i;
    if (gr < rows){
      float* outr = g_P + Poff + (size_t)gr * DV;
      #pragma unroll
      for (int p = 0; p < 4; p++){
        int j = jc + 32 * p;
        float2 a = unpack2(acc[i][p]);
        a.x += bi[j]     + bh[j];
        a.y += bi[j + 1] + bh[j + 1];
        *(float2*)(outr + j) = a;
      }
    }
  }
}

// ---------------------------------------------------------------------------
// Kernel 2: RNN recurrence via mma.sync tf32 (split-W 2-pass, role-swapped:
// A = Whh fragments (step-invariant, fragment-packed in smem),
// B = h in (k,k+4)-pair layout so each B fragment is one LDS.64).
// Computes C^T[j][m]; epilogue: h=tanh(C+P gather), mean accum, h -> pair tile.
// smem (floats): WF [2pass][8js][16kc][32lane][4] = 32768 | HP 16384 | nids 1280
// ---------------------------------------------------------------------------
#define WF_F 0
#define HP_F 32768
#define NID_F 49152
#define RNN_SMEM_BYTES ((49152 + 1280) * 4)

__global__ void __launch_bounds__(512, 1) rnn_mma_kernel(
    const float* __restrict__ Whh,
    const int* __restrict__ c_ids, const int* __restrict__ pos_ids, const int* __restrict__ neg_ids,
    const int* __restrict__ n00, const int* __restrict__ n01, const int* __restrict__ n02,
    const int* __restrict__ n10, const int* __restrict__ n11, const int* __restrict__ n12)
{
  extern __shared__ float smf[];
  float* WF = smf + WF_F;
  float* HP = smf + HP_F;
  int* nidsh = (int*)(smf + NID_F);

  const int tid  = threadIdx.x;
  const int w    = tid >> 5;
  const int lane = tid & 31;
  const int g    = lane >> 2;       // 0..7
  const int t    = lane & 3;        // 0..3

  const int y   = blockIdx.y;       // lay*9 + set*3 + nt
  const int lay = y / 9;
  const int rem = y % 9;
  const int set = rem / 3;
  const int nt  = rem % 3;
  const int ntype = (set == 0) ? 0 : 1;
  const int* ids = (set == 0) ? c_ids : ((set == 1) ? pos_ids : neg_ids);
  const int nsel = ntype * 3 + nt;
  const int* ntab = (nsel == 0) ? n00 : (nsel == 1) ? n01 : (nsel == 2) ? n02
                  : (nsel == 3) ? n10 : (nsel == 4) ? n11 : n12;
  const float* Wb = Whh + (size_t)(lay * 3 + nt) * DV * DV;
  const float* Pb = g_P + (size_t)lay * ROWS_TOT * DV
                  + (size_t)((nt == 0) ? 0 : ((nt == 1) ? CNT0 : (CNT0 + CNT1))) * DV;
  const int row0 = blockIdx.x * 128;

  // Build W fragments (hi/lo split). Each idx covers 4 elements (a0..a3).
  for (int idx = tid; idx < 4096; idx += 512){
    int l  = idx & 31;
    int kc = (idx >> 5) & 15;
    int jsb = idx >> 9;             // 0..7
    int gg = l >> 2, tt = l & 3;
    int j = 16 * jsb + gg, k = 8 * kc + tt;
    float w00 = Wb[j * DV + k];          // a0: (g,   t)
    float w10 = Wb[(j + 8) * DV + k];    // a1: (g+8, t)
    float w01 = Wb[j * DV + k + 4];      // a2: (g,   t+4)
    float w11 = Wb[(j + 8) * DV + k + 4];// a3: (g+8, t+4)
    uint4 hi, lo;
    hi.x = tf32b(w00); lo.x = tf32b(w00 - __uint_as_float(hi.x));
    hi.y = tf32b(w10); lo.y = tf32b(w10 - __uint_as_float(hi.y));
    hi.z = tf32b(w01); lo.z = tf32b(w01 - __uint_as_float(hi.z));
    hi.w = tf32b(w11); lo.w = tf32b(w11 - __uint_as_float(hi.w));
    *(uint4*)&WF[((jsb      ) * 16 + kc) * 128 + l * 4] = hi;
    *(uint4*)&WF[((jsb + 8  ) * 16 + kc) * 128 + l * 4] = lo;
  }
  for (int idx = tid; idx < 128 * NSTEP; idx += 512){
    int r = idx / NSTEP, s = idx % NSTEP;
    nidsh[idx] = ntab[(size_t)ids[row0 + r] * NSTEP + s];
  }
  __syncthreads();

  const int js = w & 7;             // j-stripe: j0..j0+15
  const int j0 = js << 4;
  const int m0base = (w >> 3) << 6; // m half: 64 rows

  float hsum[8][4];
  #pragma unroll
  for (int mt = 0; mt < 8; mt++)
    #pragma unroll
    for (int q = 0; q < 4; q++) hsum[mt][q] = 0.0f;

  float pf[4][4];                   // rolling P prefetch (depth 4)

  for (int s = 0; s < NSTEP; s++){
    // prefetch first 4 m-tiles' P values (latency hidden under MMA phase)
    #pragma unroll
    for (int mt = 0; mt < 4; mt++){
      int m0 = m0base + 8 * mt;
      int nv0 = nidsh[(m0 + 2 * t) * NSTEP + s];
      int nv1 = nidsh[(m0 + 2 * t + 1) * NSTEP + s];
      const float* P0 = Pb + (size_t)nv0 * DV;
      const float* P1 = Pb + (size_t)nv1 * DV;
      pf[mt][0] = P0[j0 + g];     pf[mt][1] = P1[j0 + g];
      pf[mt][2] = P0[j0 + g + 8]; pf[mt][3] = P1[j0 + g + 8];
    }

    float c[8][4];
    #pragma unroll
    for (int mt = 0; mt < 8; mt++)
      #pragma unroll
      for (int q = 0; q < 4; q++) c[mt][q] = 0.0f;

    if (s > 0){
      #pragma unroll 2
      for (int kc = 0; kc < 16; kc++){
        uint4 Ahi = *(const uint4*)&WF[((js    ) * 16 + kc) * 128 + lane * 4];
        uint4 Alo = *(const uint4*)&WF[((js + 8) * 16 + kc) * 128 + lane * 4];
        #pragma unroll
        for (int mt = 0; mt < 8; mt++){
          float2 b = *(const float2*)&HP[(kc * 128 + m0base + 8 * mt + g) * 8 + t * 2];
          uint32_t b0 = __float_as_uint(b.x), b1 = __float_as_uint(b.y);
          mma_tf32(c[mt], Ahi.x, Ahi.y, Ahi.z, Ahi.w, b0, b1);
          mma_tf32(c[mt], Alo.x, Alo.y, Alo.z, Alo.w, b0, b1);
        }
      }
    }
    __syncthreads();   // all HP reads (h_{s-1}) complete before overwrite

    #pragma unroll
    for (int mt = 0; mt < 8; mt++){
      // consume this tile's P values first
      float p0 = pf[mt & 3][0], p1 = pf[mt & 3][1], p2 = pf[mt & 3][2], p3 = pf[mt & 3][3];
      // then refill the freed slot (mt+4)
      if (mt < 4){
        int m0n = m0base + 8 * (mt + 4);
        int nv0 = nidsh[(m0n + 2 * t) * NSTEP + s];
        int nv1 = nidsh[(m0n + 2 * t + 1) * NSTEP + s];
        const float* P0 = Pb + (size_t)nv0 * DV;
        const float* P1 = Pb + (size_t)nv1 * DV;
        pf[mt & 3][0] = P0[j0 + g];     pf[mt & 3][1] = P1[j0 + g];
        pf[mt & 3][2] = P0[j0 + g + 8]; pf[mt & 3][3] = P1[j0 + g + 8];
      }
      int m0 = m0base + 8 * mt;
      float v0 = tanh_fast(c[mt][0] + p0);   // (j0+g,   m0+2t)
      float v1 = tanh_fast(c[mt][1] + p1);   // (j0+g,   m0+2t+1)
      float v2 = tanh_fast(c[mt][2] + p2);   // (j0+g+8, m0+2t)
      float v3 = tanh_fast(c[mt][3] + p3);   // (j0+g+8, m0+2t+1)
      hsum[mt][0] += v0; hsum[mt][1] += v1; hsum[mt][2] += v2; hsum[mt][3] += v3;
      // scatter tf32-rounded h into pair layout: HP[kc][m][ti] = (h[m][8kc+ti], h[m][8kc+ti+4])
      int pi = (g < 4) ? g : (g - 4);
      int comp = (g < 4) ? 0 : 1;
      int kcA = j0 >> 3, kcB = kcA + 1;
      uint32_t* HPu = (uint32_t*)HP;
      HPu[(kcA * 128 + m0 + 2 * t    ) * 8 + pi * 2 + comp] = tf32b(v0);
      HPu[(kcA * 128 + m0 + 2 * t + 1) * 8 + pi * 2 + comp] = tf32b(v1);
      HPu[(kcB * 128 + m0 + 2 * t    ) * 8 + pi * 2 + comp] = tf32b(v2);
      HPu[(kcB * 128 + m0 + 2 * t + 1) * 8 + pi * 2 + comp] = tf32b(v3);
    }
    __syncthreads();   // h_s visible to all warps for next step's MMA
  }

  // transpose means through HP (free now) then coalesced store
  const float inv = 1.0f / NSTEP;
  #pragma unroll
  for (int mt = 0; mt < 8; mt++){
    int m0 = m0base + 8 * mt;
    HP[(m0 + 2 * t    ) * 128 + j0 + g    ] = hsum[mt][0] * inv;
    HP[(m0 + 2 * t + 1) * 128 + j0 + g    ] = hsum[mt][1] * inv;
    HP[(m0 + 2 * t    ) * 128 + j0 + g + 8] = hsum[mt][2] * inv;
    HP[(m0 + 2 * t + 1) * 128 + j0 + g + 8] = hsum[mt][3] * inv;
  }
  __syncthreads();
  float4* ob4 = (float4*)(g_agg + ((size_t)y * BSZ + row0) * DV);
  const float4* hp4 = (const float4*)HP;
  for (int idx = tid; idx < 4096; idx += 512) ob4[idx] = hp4[idx];
}

// ---------------------------------------------------------------------------
// Kernel 3: attention over [cur, agg0, agg1, agg2], 2 layers, leaky-relu.
// ---------------------------------------------------------------------------
static __device__ __forceinline__ float breduce128(float v, float* sh){
  #pragma unroll
  for (int o = 16; o > 0; o >>= 1) v += __shfl_xor_sync(0xffffffffu, v, o);
  if ((threadIdx.x & 31) == 0) sh[threadIdx.x >> 5] = v;
  __syncthreads();
  float r = sh[0] + sh[1] + sh[2] + sh[3];
  __syncthreads();
  return r;
}

__global__ void __launch_bounds__(128) attn_kernel(
    const float* __restrict__ emb0, const float* __restrict__ emb1,
    const int* __restrict__ c_ids, const int* __restrict__ pos_ids, const int* __restrict__ neg_ids,
    const float* __restrict__ attW, float* __restrict__ out)
{
  __shared__ float sh[4];
  const int b   = blockIdx.x;
  const int set = blockIdx.y;
  const int d   = threadIdx.x;
  const int ntype = (set == 0) ? 0 : 1;
  const int* ids = (set == 0) ? c_ids : ((set == 1) ? pos_ids : neg_ids);
  const float* emb = (ntype == 0) ? emb0 : emb1;
  const int id = ids[b];
  float cur = emb[(size_t)id * DV + d];

  #pragma unroll
  for (int l = 0; l < 2; l++){
    const float* aw = attW + (size_t)(l * 3 + ntype) * 2 * DV;
    float awc = aw[d];
    float awn = aw[DV + d];
    float st0 = g_agg[((size_t)(l * 9 + set * 3 + 0) * BSZ + b) * DV + d];
    float st1 = g_agg[((size_t)(l * 9 + set * 3 + 1) * BSZ + b) * DV + d];
    float st2 = g_agg[((size_t)(l * 9 + set * 3 + 2) * BSZ + b) * DV + d];
    float base = breduce128(cur * awc, sh);
    float s0 = base + breduce128(cur * awn, sh);
    float s1 = base + breduce128(st0 * awn, sh);
    float s2 = base + breduce128(st1 * awn, sh);
    float s3 = base + breduce128(st2 * awn, sh);
    float m = fmaxf(fmaxf(s0, s1), fmaxf(s2, s3));
    float e0 = expf(s0 - m), e1 = expf(s1 - m), e2 = expf(s2 - m), e3 = expf(s3 - m);
    float inv = 1.0f / (e0 + e1 + e2 + e3);
    float v = (e0 * cur + e1 * st0 + e2 * st1 + e3 * st2) * inv;
    cur = (v > 0.0f) ? v : 0.01f * v;
  }
  out[((size_t)set * BSZ + b) * DV + d] = cur;
}

// ---------------------------------------------------------------------------
extern "C" void kernel_launch(void* const* d_in, const int* in_sizes, int n_in,
                              void* d_out, int out_size)
{
  const int*   c_ids   = (const int*)d_in[0];
  const int*   pos_ids = (const int*)d_in[1];
  const int*   neg_ids = (const int*)d_in[2];
  const int*   n00 = (const int*)d_in[3];
  const int*   n01 = (const int*)d_in[4];
  const int*   n02 = (const int*)d_in[5];
  const int*   n10 = (const int*)d_in[6];
  const int*   n11 = (const int*)d_in[7];
  const int*   n12 = (const int*)d_in[8];
  // d_in[9..11] = neigh_s2_* (unused)
  const float* emb0 = (const float*)d_in[12];
  const float* emb1 = (const float*)d_in[13];
  const float* emb2 = (const float*)d_in[14];
  const float* Wih  = (const float*)d_in[15];
  const float* Whh  = (const float*)d_in[16];
  const float* bih  = (const float*)d_in[17];
  const float* bhh  = (const float*)d_in[18];
  const float* attW = (const float*)d_in[19];

  const int smemP = (DV * 130 + DV * 264) * (int)sizeof(float);   // 201,728 B
  const int smemR = RNN_SMEM_BYTES;                                // 201,728 B
  cudaFuncSetAttribute(precompute_P_kernel, cudaFuncAttributeMaxDynamicSharedMemorySize, smemP);
  cudaFuncSetAttribute(rnn_mma_kernel,      cudaFuncAttributeMaxDynamicSharedMemorySize, smemR);

  precompute_P_kernel<<<dim3(157, 6), 512, smemP>>>(emb0, emb1, emb2, Wih, bih, bhh);
  rnn_mma_kernel<<<dim3(BSZ / 128, 18), 512, smemR>>>(Whh, c_ids, pos_ids, neg_ids,
                                                      n00, n01, n02, n10, n11, n12);
  attn_kernel<<<dim3(BSZ, 3), 128>>>(emb0, emb1, c_ids, pos_ids, neg_ids, attW, (float*)d_out);
}

// round 6
// speedup vs baseline: 2.9603x; 1.1959x over previous
#include <cuda_runtime.h>
#include <cstdint>

#define DV 128
#define NSTEP 10
#define BSZ 4096
#define CNT0 20000
#define CNT1 2000
#define CNT2 15000
#define ROWS_TOT (CNT0 + CNT1 + CNT2)

typedef unsigned long long u64;

__device__ __align__(16) float g_P[2 * ROWS_TOT * DV];     // precomputed x@Wih^T + bih + bhh
__device__ __align__(16) float g_agg[18 * BSZ * DV];       // RNN means per (l,set,nt)

static __device__ __forceinline__ float2 unpack2(u64 v){
  unsigned lo, hi;
  asm("mov.b64 {%0,%1}, %2;" : "=r"(lo), "=r"(hi) : "l"(v));
  return make_float2(__uint_as_float(lo), __uint_as_float(hi));
}
static __device__ __forceinline__ void ffma2(u64 &d, u64 a, u64 b){
  asm("fma.rn.f32x2 %0, %1, %2, %0;" : "+l"(d) : "l"(a), "l"(b));
}
static __device__ __forceinline__ float tanh_fast(float x){
  float e = __expf(2.0f * x);
  return 1.0f - __fdividef(2.0f, e + 1.0f);
}
static __device__ __forceinline__ uint32_t tf32b(float v){
  uint32_t b;
  asm("cvt.rna.tf32.f32 %0, %1;" : "=r"(b) : "f"(v));
  return b;
}
// m16n8k8 tf32 HMMA: A row-major 16x8, B col-major 8x8 (k x n), C f32 16x8
static __device__ __forceinline__ void mma_tf32(float* c,
    uint32_t a0, uint32_t a1, uint32_t a2, uint32_t a3, uint32_t b0, uint32_t b1){
  asm volatile("mma.sync.aligned.m16n8k8.row.col.f32.tf32.tf32.f32 "
    "{%0,%1,%2,%3}, {%4,%5,%6,%7}, {%8,%9}, {%0,%1,%2,%3};"
    : "+f"(c[0]), "+f"(c[1]), "+f"(c[2]), "+f"(c[3])
    : "r"(a0), "r"(a1), "r"(a2), "r"(a3), "r"(b0), "r"(b1));
}

// ---------------------------------------------------------------------------
// Kernel 1: P[l][nt] = emb[nt] @ Wih[l,nt]^T + bih + bhh (SIMT f32x2, exact).
// ---------------------------------------------------------------------------
__global__ void __launch_bounds__(512, 1) precompute_P_kernel(
    const float* __restrict__ emb0, const float* __restrict__ emb1, const float* __restrict__ emb2,
    const float* __restrict__ Wih, const float* __restrict__ bih, const float* __restrict__ bhh)
{
  extern __shared__ float sm[];
  float* Wsh = sm;               // [128][130]  W[k][j] transposed
  float* Asd = sm + DV * 130;    // [128][264]  duplicated A pairs
  const int tid  = threadIdx.x;
  const int comb = blockIdx.y;   // l*3 + nt
  const int nt   = comb % 3;
  const int l    = comb / 3;
  const int rows = (nt == 0) ? CNT0 : ((nt == 1) ? CNT1 : CNT2);
  const int row0 = blockIdx.x * 128;
  if (row0 >= rows) return;
  const float* emb = (nt == 0) ? emb0 : ((nt == 1) ? emb1 : emb2);
  const float* Wb  = Wih + (size_t)comb * DV * DV;

  for (int idx = tid; idx < DV * DV; idx += 512){
    int j = idx >> 7, k = idx & 127;
    Wsh[k * 130 + j] = Wb[idx];
  }
  for (int idx = tid; idx < 128 * 32; idx += 512){
    int r = idx >> 5, q = idx & 31;
    int gr = row0 + r;
    float4 v = make_float4(0.f, 0.f, 0.f, 0.f);
    if (gr < rows) v = *(const float4*)(emb + (size_t)gr * DV + 4 * q);
    float* dst = &Asd[r * 264 + 8 * q];
    *(float4*)(dst)     = make_float4(v.x, v.x, v.y, v.y);
    *(float4*)(dst + 4) = make_float4(v.z, v.z, v.w, v.w);
  }
  __syncthreads();

  const int r0 = (tid >> 4) * 4;
  const int jc = (tid & 15) * 2;
  u64 acc[4][4] = {};

  #pragma unroll 4
  for (int k = 0; k < DV; k++){
    const u64 b0 = *(const u64*)&Asd[(r0 + 0) * 264 + 2 * k];
    const u64 b1 = *(const u64*)&Asd[(r0 + 1) * 264 + 2 * k];
    const u64 b2 = *(const u64*)&Asd[(r0 + 2) * 264 + 2 * k];
    const u64 b3 = *(const u64*)&Asd[(r0 + 3) * 264 + 2 * k];
    const float* wr = &Wsh[k * 130 + jc];
    const u64 w0 = *(const u64*)(wr);
    const u64 w1 = *(const u64*)(wr + 32);
    const u64 w2 = *(const u64*)(wr + 64);
    const u64 w3 = *(const u64*)(wr + 96);
    ffma2(acc[0][0], b0, w0); ffma2(acc[0][1], b0, w1); ffma2(acc[0][2], b0, w2); ffma2(acc[0][3], b0, w3);
    ffma2(acc[1][0], b1, w0); ffma2(acc[1][1], b1, w1); ffma2(acc[1][2], b1, w2); ffma2(acc[1][3], b1, w3);
    ffma2(acc[2][0], b2, w0); ffma2(acc[2][1], b2, w1); ffma2(acc[2][2], b2, w2); ffma2(acc[2][3], b2, w3);
    ffma2(acc[3][0], b3, w0); ffma2(acc[3][1], b3, w1); ffma2(acc[3][2], b3, w2); ffma2(acc[3][3], b3, w3);
  }

  const float* bi = bih + (size_t)comb * DV;
  const float* bh = bhh + (size_t)comb * DV;
  const size_t Poff = (size_t)l * ROWS_TOT * DV
                    + (size_t)((nt == 0) ? 0 : ((nt == 1) ? CNT0 : (CNT0 + CNT1))) * DV;
  #pragma unroll
  for (int i = 0; i < 4; i++){
    int gr = row0 + r0 + i;
    if (gr < rows){
      float* outr = g_P + Poff + (size_t)gr * DV;
      #pragma unroll
      for (int p = 0; p < 4; p++){
        int j = jc + 32 * p;
        float2 a = unpack2(acc[i][p]);
        a.x += bi[j]     + bh[j];
        a.y += bi[j + 1] + bh[j + 1];
        *(float2*)(outr + j) = a;
      }
    }
  }
}

// ---------------------------------------------------------------------------
// Kernel 2: RNN recurrence via mma.sync tf32 (single-pass W, role-swapped:
// A = Whh fragments (step-invariant, fragment-packed in smem),
// B = h in (k,k+4)-pair layout, DOUBLE-BUFFERED -> one sync per step).
// Error budget: W tf32 rounding + h tf32 rounding ~ 2e-4 << 1e-3 gate
// (calibrated R5: h-rounding alone measured 7.1e-5 at the output).
// smem (floats): WF 16384 | HP 2x16384 | nids 1280  = 201,728 B
// ---------------------------------------------------------------------------
#define WF_F 0
#define HP_F 16384
#define NID_F 49152
#define RNN_SMEM_BYTES ((49152 + 1280) * 4)

__global__ void __launch_bounds__(512, 1) rnn_mma_kernel(
    const float* __restrict__ Whh,
    const int* __restrict__ c_ids, const int* __restrict__ pos_ids, const int* __restrict__ neg_ids,
    const int* __restrict__ n00, const int* __restrict__ n01, const int* __restrict__ n02,
    const int* __restrict__ n10, const int* __restrict__ n11, const int* __restrict__ n12)
{
  extern __shared__ float smf[];
  float* WF = smf + WF_F;
  float* HP = smf + HP_F;
  int* nidsh = (int*)(smf + NID_F);

  const int tid  = threadIdx.x;
  const int w    = tid >> 5;
  const int lane = tid & 31;
  const int g    = lane >> 2;       // 0..7
  const int t    = lane & 3;        // 0..3

  const int y   = blockIdx.y;       // lay*9 + set*3 + nt
  const int lay = y / 9;
  const int rem = y % 9;
  const int set = rem / 3;
  const int nt  = rem % 3;
  const int ntype = (set == 0) ? 0 : 1;
  const int* ids = (set == 0) ? c_ids : ((set == 1) ? pos_ids : neg_ids);
  const int nsel = ntype * 3 + nt;
  const int* ntab = (nsel == 0) ? n00 : (nsel == 1) ? n01 : (nsel == 2) ? n02
                  : (nsel == 3) ? n10 : (nsel == 4) ? n11 : n12;
  const float* Wb = Whh + (size_t)(lay * 3 + nt) * DV * DV;
  const float* Pb = g_P + (size_t)lay * ROWS_TOT * DV
                  + (size_t)((nt == 0) ? 0 : ((nt == 1) ? CNT0 : (CNT0 + CNT1))) * DV;
  const int row0 = blockIdx.x * 128;

  // Build W fragments (tf32-rna, single pass). Each idx covers one lane's a0..a3.
  for (int idx = tid; idx < 4096; idx += 512){
    int l  = idx & 31;
    int kc = (idx >> 5) & 15;
    int jsb = idx >> 9;             // 0..7
    int gg = l >> 2, tt = l & 3;
    int j = 16 * jsb + gg, k = 8 * kc + tt;
    uint4 hi;
    hi.x = tf32b(Wb[j * DV + k]);            // a0: (g,   t)
    hi.y = tf32b(Wb[(j + 8) * DV + k]);      // a1: (g+8, t)
    hi.z = tf32b(Wb[j * DV + k + 4]);        // a2: (g,   t+4)
    hi.w = tf32b(Wb[(j + 8) * DV + k + 4]);  // a3: (g+8, t+4)
    *(uint4*)&WF[(jsb * 16 + kc) * 128 + l * 4] = hi;
  }
  for (int idx = tid; idx < 128 * NSTEP; idx += 512){
    int r = idx / NSTEP, s = idx % NSTEP;
    nidsh[idx] = ntab[(size_t)ids[row0 + r] * NSTEP + s];
  }
  __syncthreads();

  const int js = w & 7;             // j-stripe: j0..j0+15
  const int j0 = js << 4;
  const int m0base = (w >> 3) << 6; // m half: 64 rows

  float hsum[8][4];
  #pragma unroll
  for (int mt = 0; mt < 8; mt++)
    #pragma unroll
    for (int q = 0; q < 4; q++) hsum[mt][q] = 0.0f;

  float pf[4][4];                   // rolling P prefetch (depth 4)

  for (int s = 0; s < NSTEP; s++){
    float* HPr = HP + (((s + 1) & 1) << 14);   // h_{s-1} (written last step)
    float* HPw = HP + ((s & 1) << 14);         // h_s (written this step)

    // prefetch first 4 m-tiles' P values (latency hidden under MMA phase)
    #pragma unroll
    for (int mt = 0; mt < 4; mt++){
      int m0 = m0base + 8 * mt;
      int nv0 = nidsh[(m0 + 2 * t) * NSTEP + s];
      int nv1 = nidsh[(m0 + 2 * t + 1) * NSTEP + s];
      const float* P0 = Pb + (size_t)nv0 * DV;
      const float* P1 = Pb + (size_t)nv1 * DV;
      pf[mt][0] = P0[j0 + g];     pf[mt][1] = P1[j0 + g];
      pf[mt][2] = P0[j0 + g + 8]; pf[mt][3] = P1[j0 + g + 8];
    }

    float c[8][4];
    #pragma unroll
    for (int mt = 0; mt < 8; mt++)
      #pragma unroll
      for (int q = 0; q < 4; q++) c[mt][q] = 0.0f;

    if (s > 0){
      #pragma unroll 2
      for (int kc = 0; kc < 16; kc++){
        uint4 A = *(const uint4*)&WF[(js * 16 + kc) * 128 + lane * 4];
        #pragma unroll
        for (int mt = 0; mt < 8; mt++){
          float2 b = *(const float2*)&HPr[(kc * 128 + m0base + 8 * mt + g) * 8 + t * 2];
          mma_tf32(c[mt], A.x, A.y, A.z, A.w,
                   __float_as_uint(b.x), __float_as_uint(b.y));
        }
      }
    }

    #pragma unroll
    for (int mt = 0; mt < 8; mt++){
      float p0 = pf[mt & 3][0], p1 = pf[mt & 3][1], p2 = pf[mt & 3][2], p3 = pf[mt & 3][3];
      if (mt < 4){  // refill freed slot (mt+4)
        int m0n = m0base + 8 * (mt + 4);
        int nv0 = nidsh[(m0n + 2 * t) * NSTEP + s];
        int nv1 = nidsh[(m0n + 2 * t + 1) * NSTEP + s];
        const float* P0 = Pb + (size_t)nv0 * DV;
        const float* P1 = Pb + (size_t)nv1 * DV;
        pf[mt & 3][0] = P0[j0 + g];     pf[mt & 3][1] = P1[j0 + g];
        pf[mt & 3][2] = P0[j0 + g + 8]; pf[mt & 3][3] = P1[j0 + g + 8];
      }
      int m0 = m0base + 8 * mt;
      float v0 = tanh_fast(c[mt][0] + p0);   // (j0+g,   m0+2t)
      float v1 = tanh_fast(c[mt][1] + p1);   // (j0+g,   m0+2t+1)
      float v2 = tanh_fast(c[mt][2] + p2);   // (j0+g+8, m0+2t)
      float v3 = tanh_fast(c[mt][3] + p3);   // (j0+g+8, m0+2t+1)
      hsum[mt][0] += v0; hsum[mt][1] += v1; hsum[mt][2] += v2; hsum[mt][3] += v3;
      // scatter tf32-rounded h into write buffer pair layout:
      // HP[kc][m][ti] = (h[m][8kc+ti], h[m][8kc+ti+4])
      int pi = (g < 4) ? g : (g - 4);
      int comp = (g < 4) ? 0 : 1;
      int kcA = j0 >> 3, kcB = kcA + 1;
      uint32_t* HPu = (uint32_t*)HPw;
      HPu[(kcA * 128 + m0 + 2 * t    ) * 8 + pi * 2 + comp] = tf32b(v0);
      HPu[(kcA * 128 + m0 + 2 * t + 1) * 8 + pi * 2 + comp] = tf32b(v1);
      HPu[(kcB * 128 + m0 + 2 * t    ) * 8 + pi * 2 + comp] = tf32b(v2);
      HPu[(kcB * 128 + m0 + 2 * t + 1) * 8 + pi * 2 + comp] = tf32b(v3);
    }
    __syncthreads();   // h_s visible to all warps for next step's MMA
  }

  // transpose means through HP buffer 0 (free now) then coalesced store
  float* HT = HP;
  const float inv = 1.0f / NSTEP;
  #pragma unroll
  for (int mt = 0; mt < 8; mt++){
    int m0 = m0base + 8 * mt;
    HT[(m0 + 2 * t    ) * 128 + j0 + g    ] = hsum[mt][0] * inv;
    HT[(m0 + 2 * t + 1) * 128 + j0 + g    ] = hsum[mt][1] * inv;
    HT[(m0 + 2 * t    ) * 128 + j0 + g + 8] = hsum[mt][2] * inv;
    HT[(m0 + 2 * t + 1) * 128 + j0 + g + 8] = hsum[mt][3] * inv;
  }
  __syncthreads();
  float4* ob4 = (float4*)(g_agg + ((size_t)y * BSZ + row0) * DV);
  const float4* hp4 = (const float4*)HT;
  for (int idx = tid; idx < 4096; idx += 512) ob4[idx] = hp4[idx];
}

// ---------------------------------------------------------------------------
// Kernel 3: attention over [cur, agg0, agg1, agg2], 2 layers, leaky-relu.
// ---------------------------------------------------------------------------
static __device__ __forceinline__ float breduce128(float v, float* sh){
  #pragma unroll
  for (int o = 16; o > 0; o >>= 1) v += __shfl_xor_sync(0xffffffffu, v, o);
  if ((threadIdx.x & 31) == 0) sh[threadIdx.x >> 5] = v;
  __syncthreads();
  float r = sh[0] + sh[1] + sh[2] + sh[3];
  __syncthreads();
  return r;
}

__global__ void __launch_bounds__(128) attn_kernel(
    const float* __restrict__ emb0, const float* __restrict__ emb1,
    const int* __restrict__ c_ids, const int* __restrict__ pos_ids, const int* __restrict__ neg_ids,
    const float* __restrict__ attW, float* __restrict__ out)
{
  __shared__ float sh[4];
  const int b   = blockIdx.x;
  const int set = blockIdx.y;
  const int d   = threadIdx.x;
  const int ntype = (set == 0) ? 0 : 1;
  const int* ids = (set == 0) ? c_ids : ((set == 1) ? pos_ids : neg_ids);
  const float* emb = (ntype == 0) ? emb0 : emb1;
  const int id = ids[b];
  float cur = emb[(size_t)id * DV + d];

  #pragma unroll
  for (int l = 0; l < 2; l++){
    const float* aw = attW + (size_t)(l * 3 + ntype) * 2 * DV;
    float awc = aw[d];
    float awn = aw[DV + d];
    float st0 = g_agg[((size_t)(l * 9 + set * 3 + 0) * BSZ + b) * DV + d];
    float st1 = g_agg[((size_t)(l * 9 + set * 3 + 1) * BSZ + b) * DV + d];
    float st2 = g_agg[((size_t)(l * 9 + set * 3 + 2) * BSZ + b) * DV + d];
    float base = breduce128(cur * awc, sh);
    float s0 = base + breduce128(cur * awn, sh);
    float s1 = base + breduce128(st0 * awn, sh);
    float s2 = base + breduce128(st1 * awn, sh);
    float s3 = base + breduce128(st2 * awn, sh);
    float m = fmaxf(fmaxf(s0, s1), fmaxf(s2, s3));
    float e0 = expf(s0 - m), e1 = expf(s1 - m), e2 = expf(s2 - m), e3 = expf(s3 - m);
    float inv = 1.0f / (e0 + e1 + e2 + e3);
    float v = (e0 * cur + e1 * st0 + e2 * st1 + e3 * st2) * inv;
    cur = (v > 0.0f) ? v : 0.01f * v;
  }
  out[((size_t)set * BSZ + b) * DV + d] = cur;
}

// ---------------------------------------------------------------------------
extern "C" void kernel_launch(void* const* d_in, const int* in_sizes, int n_in,
                              void* d_out, int out_size)
{
  const int*   c_ids   = (const int*)d_in[0];
  const int*   pos_ids = (const int*)d_in[1];
  const int*   neg_ids = (const int*)d_in[2];
  const int*   n00 = (const int*)d_in[3];
  const int*   n01 = (const int*)d_in[4];
  const int*   n02 = (const int*)d_in[5];
  const int*   n10 = (const int*)d_in[6];
  const int*   n11 = (const int*)d_in[7];
  const int*   n12 = (const int*)d_in[8];
  // d_in[9..11] = neigh_s2_* (unused)
  const float* emb0 = (const float*)d_in[12];
  const float* emb1 = (const float*)d_in[13];
  const float* emb2 = (const float*)d_in[14];
  const float* Wih  = (const float*)d_in[15];
  const float* Whh  = (const float*)d_in[16];
  const float* bih  = (const float*)d_in[17];
  const float* bhh  = (const float*)d_in[18];
  const float* attW = (const float*)d_in[19];

  const int smemP = (DV * 130 + DV * 264) * (int)sizeof(float);   // 201,728 B
  const int smemR = RNN_SMEM_BYTES;                                // 201,728 B
  cudaFuncSetAttribute(precompute_P_kernel, cudaFuncAttributeMaxDynamicSharedMemorySize, smemP);
  cudaFuncSetAttribute(rnn_mma_kernel,      cudaFuncAttributeMaxDynamicSharedMemorySize, smemR);

  precompute_P_kernel<<<dim3(157, 6), 512, smemP>>>(emb0, emb1, emb2, Wih, bih, bhh);
  rnn_mma_kernel<<<dim3(BSZ / 128, 18), 512, smemR>>>(Whh, c_ids, pos_ids, neg_ids,
                                                      n00, n01, n02, n10, n11, n12);
  attn_kernel<<<dim3(BSZ, 3), 128>>>(emb0, emb1, c_ids, pos_ids, neg_ids, attW, (float*)d_out);
}

// round 7
// speedup vs baseline: 3.2833x; 1.1091x over previous
#include <cuda_runtime.h>
#include <cstdint>

#define DV 128
#define NSTEP 10
#define BSZ 4096
#define CNT0 20000
#define CNT1 2000
#define CNT2 15000
#define ROWS_TOT (CNT0 + CNT1 + CNT2)

typedef unsigned long long u64;

__device__ __align__(16) float g_P[2 * ROWS_TOT * DV];     // precomputed x@Wih^T + bih + bhh
__device__ __align__(16) float g_agg[18 * BSZ * DV];       // RNN means per (l,set,nt)

static __device__ __forceinline__ float tanh_fast(float x){
  float e = __expf(2.0f * x);
  return 1.0f - __fdividef(2.0f, e + 1.0f);
}
static __device__ __forceinline__ uint32_t tf32b(float v){
  uint32_t b;
  asm("cvt.rna.tf32.f32 %0, %1;" : "=r"(b) : "f"(v));
  return b;
}
// m16n8k8 tf32 HMMA: A row-major 16x8, B col-major 8x8 (k x n), C f32 16x8
static __device__ __forceinline__ void mma_tf32(float* c,
    uint32_t a0, uint32_t a1, uint32_t a2, uint32_t a3, uint32_t b0, uint32_t b1){
  asm volatile("mma.sync.aligned.m16n8k8.row.col.f32.tf32.tf32.f32 "
    "{%0,%1,%2,%3}, {%4,%5,%6,%7}, {%8,%9}, {%0,%1,%2,%3};"
    : "+f"(c[0]), "+f"(c[1]), "+f"(c[2]), "+f"(c[3])
    : "r"(a0), "r"(a1), "r"(a2), "r"(a3), "r"(b0), "r"(b1));
}

// ---------------------------------------------------------------------------
// Kernel 1: P[l][nt] = emb[nt] @ Wih[l,nt]^T + bih + bhh  via HMMA tf32.
// A = Wih fragments (fragment-packed smem), B = x rows in (k,k+4)-pair layout.
// Epilogue: +biases, smem transpose, coalesced float4 store.
// smem (floats): WF 16384 | XB 16384 | OT 128*136=17408  -> 200,704 B
// ---------------------------------------------------------------------------
#define PWF 0
#define PXB 16384
#define POT 32768
#define P_SMEM_BYTES ((32768 + 128 * 136) * 4)

__global__ void __launch_bounds__(512, 1) precompute_P_kernel(
    const float* __restrict__ emb0, const float* __restrict__ emb1, const float* __restrict__ emb2,
    const float* __restrict__ Wih, const float* __restrict__ bih, const float* __restrict__ bhh)
{
  extern __shared__ float smf[];
  float* WF = smf + PWF;
  float* XB = smf + PXB;
  float* OT = smf + POT;

  const int tid  = threadIdx.x;
  const int w    = tid >> 5;
  const int lane = tid & 31;
  const int g    = lane >> 2;
  const int t    = lane & 3;

  const int comb = blockIdx.y;   // l*3 + nt
  const int nt   = comb % 3;
  const int l    = comb / 3;
  const int rows = (nt == 0) ? CNT0 : ((nt == 1) ? CNT1 : CNT2);
  const int row0 = blockIdx.x * 128;
  if (row0 >= rows) return;
  const float* emb = (nt == 0) ? emb0 : ((nt == 1) ? emb1 : emb2);
  const float* Wb  = Wih + (size_t)comb * DV * DV;

  // W fragments (tf32-rna single pass), layout identical to rnn kernel
  for (int idx = tid; idx < 4096; idx += 512){
    int ll  = idx & 31;
    int kc  = (idx >> 5) & 15;
    int jsb = idx >> 9;
    int gg = ll >> 2, tt = ll & 3;
    int j = 16 * jsb + gg, k = 8 * kc + tt;
    uint4 hi;
    hi.x = tf32b(Wb[j * DV + k]);
    hi.y = tf32b(Wb[(j + 8) * DV + k]);
    hi.z = tf32b(Wb[j * DV + k + 4]);
    hi.w = tf32b(Wb[(j + 8) * DV + k + 4]);
    *(uint4*)&WF[(jsb * 16 + kc) * 128 + ll * 4] = hi;
  }
  // x tile into (k,k+4)-pair layout, tf32-rounded
  {
    uint32_t* XBu = (uint32_t*)XB;
    for (int idx = tid; idx < 4096; idx += 512){
      int m = idx >> 5, q = idx & 31;
      int gr = row0 + m;
      float4 v = make_float4(0.f, 0.f, 0.f, 0.f);
      if (gr < rows) v = *(const float4*)(emb + (size_t)gr * DV + 4 * q);
      const float* ve = (const float*)&v;
      #pragma unroll
      for (int e = 0; e < 4; e++){
        int k = 4 * q + e;
        XBu[((k >> 3) * 128 + m) * 8 + (k & 3) * 2 + ((k >> 2) & 1)] = tf32b(ve[e]);
      }
    }
  }
  __syncthreads();

  const int js = w & 7;
  const int j0 = js << 4;
  const int m0base = (w >> 3) << 6;

  float c[8][4];
  #pragma unroll
  for (int mt = 0; mt < 8; mt++)
    #pragma unroll
    for (int q = 0; q < 4; q++) c[mt][q] = 0.0f;

  #pragma unroll 2
  for (int kc = 0; kc < 16; kc++){
    uint4 A = *(const uint4*)&WF[(js * 16 + kc) * 128 + lane * 4];
    #pragma unroll
    for (int mt = 0; mt < 8; mt++){
      float2 b = *(const float2*)&XB[(kc * 128 + m0base + 8 * mt + g) * 8 + t * 2];
      mma_tf32(c[mt], A.x, A.y, A.z, A.w,
               __float_as_uint(b.x), __float_as_uint(b.y));
    }
  }

  const float bj0 = bih[(size_t)comb * DV + j0 + g]     + bhh[(size_t)comb * DV + j0 + g];
  const float bj8 = bih[(size_t)comb * DV + j0 + g + 8] + bhh[(size_t)comb * DV + j0 + g + 8];

  #pragma unroll
  for (int mt = 0; mt < 8; mt++){
    int m0 = m0base + 8 * mt;
    OT[(m0 + 2 * t    ) * 136 + j0 + g    ] = c[mt][0] + bj0;
    OT[(m0 + 2 * t + 1) * 136 + j0 + g    ] = c[mt][1] + bj0;
    OT[(m0 + 2 * t    ) * 136 + j0 + g + 8] = c[mt][2] + bj8;
    OT[(m0 + 2 * t + 1) * 136 + j0 + g + 8] = c[mt][3] + bj8;
  }
  __syncthreads();

  const size_t Poff = (size_t)l * ROWS_TOT * DV
                    + (size_t)((nt == 0) ? 0 : ((nt == 1) ? CNT0 : (CNT0 + CNT1))) * DV;
  for (int idx = tid; idx < 4096; idx += 512){
    int m = idx >> 5, q = idx & 31;
    int gr = row0 + m;
    if (gr < rows)
      *(float4*)(g_P + Poff + (size_t)gr * DV + 4 * q) = *(const float4*)&OT[m * 136 + 4 * q];
  }
}

// ---------------------------------------------------------------------------
// Kernel 2: RNN recurrence via mma.sync tf32 (single-pass W, role-swapped:
// A = Whh fragments, B = h in (k,k+4)-pair layout, double-buffered).
// P-gather for all 8 m-tiles prefetched before the epilogue (depth 4+4).
// smem (floats): WF 16384 | HP 2x16384 | nids 1280 = 201,728 B
// ---------------------------------------------------------------------------
#define WF_F 0
#define HP_F 16384
#define NID_F 49152
#define RNN_SMEM_BYTES ((49152 + 1280) * 4)

__global__ void __launch_bounds__(512, 1) rnn_mma_kernel(
    const float* __restrict__ Whh,
    const int* __restrict__ c_ids, const int* __restrict__ pos_ids, const int* __restrict__ neg_ids,
    const int* __restrict__ n00, const int* __restrict__ n01, const int* __restrict__ n02,
    const int* __restrict__ n10, const int* __restrict__ n11, const int* __restrict__ n12)
{
  extern __shared__ float smf[];
  float* WF = smf + WF_F;
  float* HP = smf + HP_F;
  int* nidsh = (int*)(smf + NID_F);

  const int tid  = threadIdx.x;
  const int w    = tid >> 5;
  const int lane = tid & 31;
  const int g    = lane >> 2;
  const int t    = lane & 3;

  const int y   = blockIdx.y;       // lay*9 + set*3 + nt
  const int lay = y / 9;
  const int rem = y % 9;
  const int set = rem / 3;
  const int nt  = rem % 3;
  const int ntype = (set == 0) ? 0 : 1;
  const int* ids = (set == 0) ? c_ids : ((set == 1) ? pos_ids : neg_ids);
  const int nsel = ntype * 3 + nt;
  const int* ntab = (nsel == 0) ? n00 : (nsel == 1) ? n01 : (nsel == 2) ? n02
                  : (nsel == 3) ? n10 : (nsel == 4) ? n11 : n12;
  const float* Wb = Whh + (size_t)(lay * 3 + nt) * DV * DV;
  const float* Pb = g_P + (size_t)lay * ROWS_TOT * DV
                  + (size_t)((nt == 0) ? 0 : ((nt == 1) ? CNT0 : (CNT0 + CNT1))) * DV;
  const int row0 = blockIdx.x * 128;

  // W fragments (tf32-rna single pass)
  for (int idx = tid; idx < 4096; idx += 512){
    int ll  = idx & 31;
    int kc  = (idx >> 5) & 15;
    int jsb = idx >> 9;
    int gg = ll >> 2, tt = ll & 3;
    int j = 16 * jsb + gg, k = 8 * kc + tt;
    uint4 hi;
    hi.x = tf32b(Wb[j * DV + k]);
    hi.y = tf32b(Wb[(j + 8) * DV + k]);
    hi.z = tf32b(Wb[j * DV + k + 4]);
    hi.w = tf32b(Wb[(j + 8) * DV + k + 4]);
    *(uint4*)&WF[(jsb * 16 + kc) * 128 + ll * 4] = hi;
  }
  for (int idx = tid; idx < 128 * NSTEP; idx += 512){
    int r = idx / NSTEP, s = idx % NSTEP;
    nidsh[idx] = ntab[(size_t)ids[row0 + r] * NSTEP + s];
  }
  __syncthreads();

  const int js = w & 7;             // j-stripe: j0..j0+15
  const int j0 = js << 4;
  const int m0base = (w >> 3) << 6; // m half: 64 rows

  float hsum[8][4];
  #pragma unroll
  for (int mt = 0; mt < 8; mt++)
    #pragma unroll
    for (int q = 0; q < 4; q++) hsum[mt][q] = 0.0f;

  float pf[4][4], pf2[4][4];

  for (int s = 0; s < NSTEP; s++){
    float* HPr = HP + (((s + 1) & 1) << 14);   // h_{s-1}
    float* HPw = HP + ((s & 1) << 14);         // h_s

    // prefetch m-tiles 0..3 (latency hidden under MMA phase)
    #pragma unroll
    for (int mt = 0; mt < 4; mt++){
      int m0 = m0base + 8 * mt;
      int nv0 = nidsh[(m0 + 2 * t) * NSTEP + s];
      int nv1 = nidsh[(m0 + 2 * t + 1) * NSTEP + s];
      const float* P0 = Pb + (size_t)nv0 * DV;
      const float* P1 = Pb + (size_t)nv1 * DV;
      pf[mt][0] = P0[j0 + g];     pf[mt][1] = P1[j0 + g];
      pf[mt][2] = P0[j0 + g + 8]; pf[mt][3] = P1[j0 + g + 8];
    }

    float c[8][4];
    #pragma unroll
    for (int mt = 0; mt < 8; mt++)
      #pragma unroll
      for (int q = 0; q < 4; q++) c[mt][q] = 0.0f;

    if (s > 0){
      #pragma unroll 2
      for (int kc = 0; kc < 16; kc++){
        uint4 A = *(const uint4*)&WF[(js * 16 + kc) * 128 + lane * 4];
        #pragma unroll
        for (int mt = 0; mt < 8; mt++){
          float2 b = *(const float2*)&HPr[(kc * 128 + m0base + 8 * mt + g) * 8 + t * 2];
          mma_tf32(c[mt], A.x, A.y, A.z, A.w,
                   __float_as_uint(b.x), __float_as_uint(b.y));
        }
      }
    }

    // prefetch m-tiles 4..7 before any tanh (all LDGs in flight)
    #pragma unroll
    for (int mt = 0; mt < 4; mt++){
      int m0 = m0base + 8 * (mt + 4);
      int nv0 = nidsh[(m0 + 2 * t) * NSTEP + s];
      int nv1 = nidsh[(m0 + 2 * t + 1) * NSTEP + s];
      const float* P0 = Pb + (size_t)nv0 * DV;
      const float* P1 = Pb + (size_t)nv1 * DV;
      pf2[mt][0] = P0[j0 + g];     pf2[mt][1] = P1[j0 + g];
      pf2[mt][2] = P0[j0 + g + 8]; pf2[mt][3] = P1[j0 + g + 8];
    }

    #pragma unroll
    for (int mt = 0; mt < 8; mt++){
      const float* pp = (mt < 4) ? pf[mt] : pf2[mt - 4];
      int m0 = m0base + 8 * mt;
      float v0 = tanh_fast(c[mt][0] + pp[0]);   // (j0+g,   m0+2t)
      float v1 = tanh_fast(c[mt][1] + pp[1]);   // (j0+g,   m0+2t+1)
      float v2 = tanh_fast(c[mt][2] + pp[2]);   // (j0+g+8, m0+2t)
      float v3 = tanh_fast(c[mt][3] + pp[3]);   // (j0+g+8, m0+2t+1)
      hsum[mt][0] += v0; hsum[mt][1] += v1; hsum[mt][2] += v2; hsum[mt][3] += v3;
      // scatter tf32-rounded h into write buffer pair layout
      int pi = (g < 4) ? g : (g - 4);
      int comp = (g < 4) ? 0 : 1;
      int kcA = j0 >> 3, kcB = kcA + 1;
      uint32_t* HPu = (uint32_t*)HPw;
      HPu[(kcA * 128 + m0 + 2 * t    ) * 8 + pi * 2 + comp] = tf32b(v0);
      HPu[(kcA * 128 + m0 + 2 * t + 1) * 8 + pi * 2 + comp] = tf32b(v1);
      HPu[(kcB * 128 + m0 + 2 * t    ) * 8 + pi * 2 + comp] = tf32b(v2);
      HPu[(kcB * 128 + m0 + 2 * t + 1) * 8 + pi * 2 + comp] = tf32b(v3);
    }
    __syncthreads();   // h_s visible to all warps for next step's MMA
  }

  // transpose means through HP buffer 0 (free now) then coalesced store
  float* HT = HP;
  const float inv = 1.0f / NSTEP;
  #pragma unroll
  for (int mt = 0; mt < 8; mt++){
    int m0 = m0base + 8 * mt;
    HT[(m0 + 2 * t    ) * 128 + j0 + g    ] = hsum[mt][0] * inv;
    HT[(m0 + 2 * t + 1) * 128 + j0 + g    ] = hsum[mt][1] * inv;
    HT[(m0 + 2 * t    ) * 128 + j0 + g + 8] = hsum[mt][2] * inv;
    HT[(m0 + 2 * t + 1) * 128 + j0 + g + 8] = hsum[mt][3] * inv;
  }
  __syncthreads();
  float4* ob4 = (float4*)(g_agg + ((size_t)y * BSZ + row0) * DV);
  const float4* hp4 = (const float4*)HT;
  for (int idx = tid; idx < 4096; idx += 512) ob4[idx] = hp4[idx];
}

// ---------------------------------------------------------------------------
// Kernel 3: attention over [cur, agg0, agg1, agg2], 2 layers, leaky-relu.
// ---------------------------------------------------------------------------
static __device__ __forceinline__ float breduce128(float v, float* sh){
  #pragma unroll
  for (int o = 16; o > 0; o >>= 1) v += __shfl_xor_sync(0xffffffffu, v, o);
  if ((threadIdx.x & 31) == 0) sh[threadIdx.x >> 5] = v;
  __syncthreads();
  float r = sh[0] + sh[1] + sh[2] + sh[3];
  __syncthreads();
  return r;
}

__global__ void __launch_bounds__(128) attn_kernel(
    const float* __restrict__ emb0, const float* __restrict__ emb1,
    const int* __restrict__ c_ids, const int* __restrict__ pos_ids, const int* __restrict__ neg_ids,
    const float* __restrict__ attW, float* __restrict__ out)
{
  __shared__ float sh[4];
  const int b   = blockIdx.x;
  const int set = blockIdx.y;
  const int d   = threadIdx.x;
  const int ntype = (set == 0) ? 0 : 1;
  const int* ids = (set == 0) ? c_ids : ((set == 1) ? pos_ids : neg_ids);
  const float* emb = (ntype == 0) ? emb0 : emb1;
  const int id = ids[b];
  float cur = emb[(size_t)id * DV + d];

  #pragma unroll
  for (int l = 0; l < 2; l++){
    const float* aw = attW + (size_t)(l * 3 + ntype) * 2 * DV;
    float awc = aw[d];
    float awn = aw[DV + d];
    float st0 = g_agg[((size_t)(l * 9 + set * 3 + 0) * BSZ + b) * DV + d];
    float st1 = g_agg[((size_t)(l * 9 + set * 3 + 1) * BSZ + b) * DV + d];
    float st2 = g_agg[((size_t)(l * 9 + set * 3 + 2) * BSZ + b) * DV + d];
    float base = breduce128(cur * awc, sh);
    float s0 = base + breduce128(cur * awn, sh);
    float s1 = base + breduce128(st0 * awn, sh);
    float s2 = base + breduce128(st1 * awn, sh);
    float s3 = base + breduce128(st2 * awn, sh);
    float m = fmaxf(fmaxf(s0, s1), fmaxf(s2, s3));
    float e0 = expf(s0 - m), e1 = expf(s1 - m), e2 = expf(s2 - m), e3 = expf(s3 - m);
    float inv = 1.0f / (e0 + e1 + e2 + e3);
    float v = (e0 * cur + e1 * st0 + e2 * st1 + e3 * st2) * inv;
    cur = (v > 0.0f) ? v : 0.01f * v;
  }
  out[((size_t)set * BSZ + b) * DV + d] = cur;
}

// ---------------------------------------------------------------------------
extern "C" void kernel_launch(void* const* d_in, const int* in_sizes, int n_in,
                              void* d_out, int out_size)
{
  const int*   c_ids   = (const int*)d_in[0];
  const int*   pos_ids = (const int*)d_in[1];
  const int*   neg_ids = (const int*)d_in[2];
  const int*   n00 = (const int*)d_in[3];
  const int*   n01 = (const int*)d_in[4];
  const int*   n02 = (const int*)d_in[5];
  const int*   n10 = (const int*)d_in[6];
  const int*   n11 = (const int*)d_in[7];
  const int*   n12 = (const int*)d_in[8];
  // d_in[9..11] = neigh_s2_* (unused)
  const float* emb0 = (const float*)d_in[12];
  const float* emb1 = (const float*)d_in[13];
  const float* emb2 = (const float*)d_in[14];
  const float* Wih  = (const float*)d_in[15];
  const float* Whh  = (const float*)d_in[16];
  const float* bih  = (const float*)d_in[17];
  const float* bhh  = (const float*)d_in[18];
  const float* attW = (const float*)d_in[19];

  cudaFuncSetAttribute(precompute_P_kernel, cudaFuncAttributeMaxDynamicSharedMemorySize, P_SMEM_BYTES);
  cudaFuncSetAttribute(rnn_mma_kernel,      cudaFuncAttributeMaxDynamicSharedMemorySize, RNN_SMEM_BYTES);

  precompute_P_kernel<<<dim3(157, 6), 512, P_SMEM_BYTES>>>(emb0, emb1, emb2, Wih, bih, bhh);
  rnn_mma_kernel<<<dim3(BSZ / 128, 18), 512, RNN_SMEM_BYTES>>>(Whh, c_ids, pos_ids, neg_ids,
                                                               n00, n01, n02, n10, n11, n12);
  attn_kernel<<<dim3(BSZ, 3), 128>>>(emb0, emb1, c_ids, pos_ids, neg_ids, attW, (float*)d_out);
}

// round 8
// speedup vs baseline: 5.0904x; 1.5504x over previous
#include <cuda_runtime.h>
#include <cstdint>

#define DV 128
#define NSTEP 10
#define BSZ 4096
#define CNT0 20000
#define CNT1 2000
#define CNT2 15000
#define ROWS_TOT (CNT0 + CNT1 + CNT2)
#define T1PAD 2048   // type-1 node count padded to tile multiple

typedef unsigned long long u64;

__device__ __align__(16) float g_P[2 * ROWS_TOT * DV];          // x@Wih^T + bih + bhh
__device__ __align__(16) float g_aggC[6 * BSZ * DV];            // c-set RNN means  [lay*3+nt][b]
__device__ __align__(16) float g_aggT[6 * T1PAD * DV];          // type-1 RNN means [lay*3+nt][node]
__device__ __align__(16) float g_attnT[T1PAD * DV];             // type-1 attention output per node

static __device__ __forceinline__ float tanh_fast(float x){
  float e = __expf(2.0f * x);
  return 1.0f - __fdividef(2.0f, e + 1.0f);
}
static __device__ __forceinline__ uint32_t tf32b(float v){
  uint32_t b;
  asm("cvt.rna.tf32.f32 %0, %1;" : "=r"(b) : "f"(v));
  return b;
}
// m16n8k8 tf32 HMMA: A row-major 16x8, B col-major 8x8 (k x n), C f32 16x8
static __device__ __forceinline__ void mma_tf32(float* c,
    uint32_t a0, uint32_t a1, uint32_t a2, uint32_t a3, uint32_t b0, uint32_t b1){
  asm volatile("mma.sync.aligned.m16n8k8.row.col.f32.tf32.tf32.f32 "
    "{%0,%1,%2,%3}, {%4,%5,%6,%7}, {%8,%9}, {%0,%1,%2,%3};"
    : "+f"(c[0]), "+f"(c[1]), "+f"(c[2]), "+f"(c[3])
    : "r"(a0), "r"(a1), "r"(a2), "r"(a3), "r"(b0), "r"(b1));
}

// ---------------------------------------------------------------------------
// Kernel 1: P[l][nt] = emb[nt] @ Wih[l,nt]^T + bih + bhh  via HMMA tf32.
// ---------------------------------------------------------------------------
#define PWF 0
#define PXB 16384
#define POT 32768
#define P_SMEM_BYTES ((32768 + 128 * 136) * 4)

__global__ void __launch_bounds__(512, 1) precompute_P_kernel(
    const float* __restrict__ emb0, const float* __restrict__ emb1, const float* __restrict__ emb2,
    const float* __restrict__ Wih, const float* __restrict__ bih, const float* __restrict__ bhh)
{
  extern __shared__ float smf[];
  float* WF = smf + PWF;
  float* XB = smf + PXB;
  float* OT = smf + POT;

  const int tid  = threadIdx.x;
  const int w    = tid >> 5;
  const int lane = tid & 31;
  const int g    = lane >> 2;
  const int t    = lane & 3;

  const int comb = blockIdx.y;   // l*3 + nt
  const int nt   = comb % 3;
  const int l    = comb / 3;
  const int rows = (nt == 0) ? CNT0 : ((nt == 1) ? CNT1 : CNT2);
  const int row0 = blockIdx.x * 128;
  if (row0 >= rows) return;
  const float* emb = (nt == 0) ? emb0 : ((nt == 1) ? emb1 : emb2);
  const float* Wb  = Wih + (size_t)comb * DV * DV;

  for (int idx = tid; idx < 4096; idx += 512){
    int ll  = idx & 31;
    int kc  = (idx >> 5) & 15;
    int jsb = idx >> 9;
    int gg = ll >> 2, tt = ll & 3;
    int j = 16 * jsb + gg, k = 8 * kc + tt;
    uint4 hi;
    hi.x = tf32b(Wb[j * DV + k]);
    hi.y = tf32b(Wb[(j + 8) * DV + k]);
    hi.z = tf32b(Wb[j * DV + k + 4]);
    hi.w = tf32b(Wb[(j + 8) * DV + k + 4]);
    *(uint4*)&WF[(jsb * 16 + kc) * 128 + ll * 4] = hi;
  }
  {
    uint32_t* XBu = (uint32_t*)XB;
    for (int idx = tid; idx < 4096; idx += 512){
      int m = idx >> 5, q = idx & 31;
      int gr = row0 + m;
      float4 v = make_float4(0.f, 0.f, 0.f, 0.f);
      if (gr < rows) v = *(const float4*)(emb + (size_t)gr * DV + 4 * q);
      const float* ve = (const float*)&v;
      #pragma unroll
      for (int e = 0; e < 4; e++){
        int k = 4 * q + e;
        XBu[((k >> 3) * 128 + m) * 8 + (k & 3) * 2 + ((k >> 2) & 1)] = tf32b(ve[e]);
      }
    }
  }
  __syncthreads();

  const int js = w & 7;
  const int j0 = js << 4;
  const int m0base = (w >> 3) << 6;

  float c[8][4];
  #pragma unroll
  for (int mt = 0; mt < 8; mt++)
    #pragma unroll
    for (int q = 0; q < 4; q++) c[mt][q] = 0.0f;

  #pragma unroll 2
  for (int kc = 0; kc < 16; kc++){
    uint4 A = *(const uint4*)&WF[(js * 16 + kc) * 128 + lane * 4];
    #pragma unroll
    for (int mt = 0; mt < 8; mt++){
      float2 b = *(const float2*)&XB[(kc * 128 + m0base + 8 * mt + g) * 8 + t * 2];
      mma_tf32(c[mt], A.x, A.y, A.z, A.w,
               __float_as_uint(b.x), __float_as_uint(b.y));
    }
  }

  const float bj0 = bih[(size_t)comb * DV + j0 + g]     + bhh[(size_t)comb * DV + j0 + g];
  const float bj8 = bih[(size_t)comb * DV + j0 + g + 8] + bhh[(size_t)comb * DV + j0 + g + 8];

  #pragma unroll
  for (int mt = 0; mt < 8; mt++){
    int m0 = m0base + 8 * mt;
    OT[(m0 + 2 * t    ) * 136 + j0 + g    ] = c[mt][0] + bj0;
    OT[(m0 + 2 * t + 1) * 136 + j0 + g    ] = c[mt][1] + bj0;
    OT[(m0 + 2 * t    ) * 136 + j0 + g + 8] = c[mt][2] + bj8;
    OT[(m0 + 2 * t + 1) * 136 + j0 + g + 8] = c[mt][3] + bj8;
  }
  __syncthreads();

  const size_t Poff = (size_t)l * ROWS_TOT * DV
                    + (size_t)((nt == 0) ? 0 : ((nt == 1) ? CNT0 : (CNT0 + CNT1))) * DV;
  for (int idx = tid; idx < 4096; idx += 512){
    int m = idx >> 5, q = idx & 31;
    int gr = row0 + m;
    if (gr < rows)
      *(float4*)(g_P + Poff + (size_t)gr * DV + 4 * q) = *(const float4*)&OT[m * 136 + 4 * q];
  }
}

// ---------------------------------------------------------------------------
// Kernel 2: RNN via mma.sync tf32. DEDUPED: grid.x = 48 tiles/(lay,nt):
//   x in [0,32): c-set rows (ids = c_ids)          -> g_aggC
//   x in [32,48): ALL type-1 nodes (ids = row idx) -> g_aggT  (computed once,
//   gathered later by pos_ids/neg_ids — reference recomputes each ~4.1x)
// ---------------------------------------------------------------------------
#define WF_F 0
#define HP_F 16384
#define NID_F 49152
#define RNN_SMEM_BYTES ((49152 + 1280) * 4)

__global__ void __launch_bounds__(512, 1) rnn_mma_kernel(
    const float* __restrict__ Whh,
    const int* __restrict__ c_ids,
    const int* __restrict__ n00, const int* __restrict__ n01, const int* __restrict__ n02,
    const int* __restrict__ n10, const int* __restrict__ n11, const int* __restrict__ n12)
{
  extern __shared__ float smf[];
  float* WF = smf + WF_F;
  float* HP = smf + HP_F;
  int* nidsh = (int*)(smf + NID_F);

  const int tid  = threadIdx.x;
  const int w    = tid >> 5;
  const int lane = tid & 31;
  const int g    = lane >> 2;
  const int t    = lane & 3;

  const int y   = blockIdx.y;       // lay*3 + nt
  const int lay = y / 3;
  const int nt  = y % 3;
  const int xb  = blockIdx.x;
  const bool isT = (xb >= 32);
  const int ntype = isT ? 1 : 0;
  const int row0  = (isT ? (xb - 32) : xb) * 128;
  const int nsel = ntype * 3 + nt;
  const int* ntab = (nsel == 0) ? n00 : (nsel == 1) ? n01 : (nsel == 2) ? n02
                  : (nsel == 3) ? n10 : (nsel == 4) ? n11 : n12;
  const float* Wb = Whh + (size_t)(lay * 3 + nt) * DV * DV;
  const float* Pb = g_P + (size_t)lay * ROWS_TOT * DV
                  + (size_t)((nt == 0) ? 0 : ((nt == 1) ? CNT0 : (CNT0 + CNT1))) * DV;

  // W fragments (tf32-rna single pass)
  for (int idx = tid; idx < 4096; idx += 512){
    int ll  = idx & 31;
    int kc  = (idx >> 5) & 15;
    int jsb = idx >> 9;
    int gg = ll >> 2, tt = ll & 3;
    int j = 16 * jsb + gg, k = 8 * kc + tt;
    uint4 hi;
    hi.x = tf32b(Wb[j * DV + k]);
    hi.y = tf32b(Wb[(j + 8) * DV + k]);
    hi.z = tf32b(Wb[j * DV + k + 4]);
    hi.w = tf32b(Wb[(j + 8) * DV + k + 4]);
    *(uint4*)&WF[(jsb * 16 + kc) * 128 + ll * 4] = hi;
  }
  for (int idx = tid; idx < 128 * NSTEP; idx += 512){
    int r = idx / NSTEP, s = idx % NSTEP;
    int id = isT ? min(row0 + r, CNT1 - 1) : c_ids[row0 + r];
    nidsh[idx] = ntab[(size_t)id * NSTEP + s];
  }
  __syncthreads();

  const int js = w & 7;             // j-stripe
  const int j0 = js << 4;
  const int m0base = (w >> 3) << 6; // m half

  float hsum[8][4];
  #pragma unroll
  for (int mt = 0; mt < 8; mt++)
    #pragma unroll
    for (int q = 0; q < 4; q++) hsum[mt][q] = 0.0f;

  float pf[4][4], pf2[4][4];

  for (int s = 0; s < NSTEP; s++){
    float* HPr = HP + (((s + 1) & 1) << 14);
    float* HPw = HP + ((s & 1) << 14);

    #pragma unroll
    for (int mt = 0; mt < 4; mt++){
      int m0 = m0base + 8 * mt;
      int nv0 = nidsh[(m0 + 2 * t) * NSTEP + s];
      int nv1 = nidsh[(m0 + 2 * t + 1) * NSTEP + s];
      const float* P0 = Pb + (size_t)nv0 * DV;
      const float* P1 = Pb + (size_t)nv1 * DV;
      pf[mt][0] = P0[j0 + g];     pf[mt][1] = P1[j0 + g];
      pf[mt][2] = P0[j0 + g + 8]; pf[mt][3] = P1[j0 + g + 8];
    }

    float c[8][4];
    #pragma unroll
    for (int mt = 0; mt < 8; mt++)
      #pragma unroll
      for (int q = 0; q < 4; q++) c[mt][q] = 0.0f;

    if (s > 0){
      #pragma unroll 2
      for (int kc = 0; kc < 16; kc++){
        uint4 A = *(const uint4*)&WF[(js * 16 + kc) * 128 + lane * 4];
        #pragma unroll
        for (int mt = 0; mt < 8; mt++){
          float2 b = *(const float2*)&HPr[(kc * 128 + m0base + 8 * mt + g) * 8 + t * 2];
          mma_tf32(c[mt], A.x, A.y, A.z, A.w,
                   __float_as_uint(b.x), __float_as_uint(b.y));
        }
      }
    }

    #pragma unroll
    for (int mt = 0; mt < 4; mt++){
      int m0 = m0base + 8 * (mt + 4);
      int nv0 = nidsh[(m0 + 2 * t) * NSTEP + s];
      int nv1 = nidsh[(m0 + 2 * t + 1) * NSTEP + s];
      const float* P0 = Pb + (size_t)nv0 * DV;
      const float* P1 = Pb + (size_t)nv1 * DV;
      pf2[mt][0] = P0[j0 + g];     pf2[mt][1] = P1[j0 + g];
      pf2[mt][2] = P0[j0 + g + 8]; pf2[mt][3] = P1[j0 + g + 8];
    }

    #pragma unroll
    for (int mt = 0; mt < 8; mt++){
      const float* pp = (mt < 4) ? pf[mt] : pf2[mt - 4];
      int m0 = m0base + 8 * mt;
      float v0 = tanh_fast(c[mt][0] + pp[0]);
      float v1 = tanh_fast(c[mt][1] + pp[1]);
      float v2 = tanh_fast(c[mt][2] + pp[2]);
      float v3 = tanh_fast(c[mt][3] + pp[3]);
      hsum[mt][0] += v0; hsum[mt][1] += v1; hsum[mt][2] += v2; hsum[mt][3] += v3;
      int pi = (g < 4) ? g : (g - 4);
      int comp = (g < 4) ? 0 : 1;
      int kcA = j0 >> 3, kcB = kcA + 1;
      uint32_t* HPu = (uint32_t*)HPw;
      HPu[(kcA * 128 + m0 + 2 * t    ) * 8 + pi * 2 + comp] = tf32b(v0);
      HPu[(kcA * 128 + m0 + 2 * t + 1) * 8 + pi * 2 + comp] = tf32b(v1);
      HPu[(kcB * 128 + m0 + 2 * t    ) * 8 + pi * 2 + comp] = tf32b(v2);
      HPu[(kcB * 128 + m0 + 2 * t + 1) * 8 + pi * 2 + comp] = tf32b(v3);
    }
    __syncthreads();
  }

  float* HT = HP;
  const float inv = 1.0f / NSTEP;
  #pragma unroll
  for (int mt = 0; mt < 8; mt++){
    int m0 = m0base + 8 * mt;
    HT[(m0 + 2 * t    ) * 128 + j0 + g    ] = hsum[mt][0] * inv;
    HT[(m0 + 2 * t + 1) * 128 + j0 + g    ] = hsum[mt][1] * inv;
    HT[(m0 + 2 * t    ) * 128 + j0 + g + 8] = hsum[mt][2] * inv;
    HT[(m0 + 2 * t + 1) * 128 + j0 + g + 8] = hsum[mt][3] * inv;
  }
  __syncthreads();
  float* ob = isT ? (g_aggT + ((size_t)y * T1PAD + row0) * DV)
                  : (g_aggC + ((size_t)y * BSZ  + row0) * DV);
  float4* ob4 = (float4*)ob;
  const float4* hp4 = (const float4*)HT;
  for (int idx = tid; idx < 4096; idx += 512) ob4[idx] = hp4[idx];
}

// ---------------------------------------------------------------------------
// Kernel 3: attention. b < BSZ: c-set rows -> out[0]. b >= BSZ: type-1 node
// (b-BSZ) -> g_attnT (computed once per node).
// ---------------------------------------------------------------------------
static __device__ __forceinline__ float breduce128(float v, float* sh){
  #pragma unroll
  for (int o = 16; o > 0; o >>= 1) v += __shfl_xor_sync(0xffffffffu, v, o);
  if ((threadIdx.x & 31) == 0) sh[threadIdx.x >> 5] = v;
  __syncthreads();
  float r = sh[0] + sh[1] + sh[2] + sh[3];
  __syncthreads();
  return r;
}

__global__ void __launch_bounds__(128) attn_kernel(
    const float* __restrict__ emb0, const float* __restrict__ emb1,
    const int* __restrict__ c_ids,
    const float* __restrict__ attW, float* __restrict__ out)
{
  __shared__ float sh[4];
  const int b  = blockIdx.x;
  const int d  = threadIdx.x;
  const bool isT = (b >= BSZ);
  const int node = b - BSZ;
  if (isT && node >= CNT1) return;
  const int ntype = isT ? 1 : 0;
  const float* agg = isT ? g_aggT : g_aggC;
  const int nrows  = isT ? T1PAD : BSZ;
  const int ridx   = isT ? node : b;
  float cur = isT ? emb1[(size_t)node * DV + d] : emb0[(size_t)c_ids[b] * DV + d];

  #pragma unroll
  for (int l = 0; l < 2; l++){
    const float* aw = attW + (size_t)(l * 3 + ntype) * 2 * DV;
    float awc = aw[d];
    float awn = aw[DV + d];
    float st0 = agg[((size_t)(l * 3 + 0) * nrows + ridx) * DV + d];
    float st1 = agg[((size_t)(l * 3 + 1) * nrows + ridx) * DV + d];
    float st2 = agg[((size_t)(l * 3 + 2) * nrows + ridx) * DV + d];
    float base = breduce128(cur * awc, sh);
    float s0 = base + breduce128(cur * awn, sh);
    float s1 = base + breduce128(st0 * awn, sh);
    float s2 = base + breduce128(st1 * awn, sh);
    float s3 = base + breduce128(st2 * awn, sh);
    float m = fmaxf(fmaxf(s0, s1), fmaxf(s2, s3));
    float e0 = expf(s0 - m), e1 = expf(s1 - m), e2 = expf(s2 - m), e3 = expf(s3 - m);
    float inv = 1.0f / (e0 + e1 + e2 + e3);
    float v = (e0 * cur + e1 * st0 + e2 * st1 + e3 * st2) * inv;
    cur = (v > 0.0f) ? v : 0.01f * v;
  }
  if (isT) g_attnT[(size_t)node * DV + d] = cur;
  else     out[(size_t)b * DV + d] = cur;
}

// Kernel 4: gather type-1 attention outputs by pos/neg ids.
__global__ void __launch_bounds__(128) scatter_kernel(
    const int* __restrict__ pos_ids, const int* __restrict__ neg_ids,
    float* __restrict__ out)
{
  const int b   = blockIdx.x;
  const int set = blockIdx.y;        // 0 -> pos (out set1), 1 -> neg (out set2)
  const int d   = threadIdx.x;
  const int id  = set ? neg_ids[b] : pos_ids[b];
  out[((size_t)(set + 1) * BSZ + b) * DV + d] = g_attnT[(size_t)id * DV + d];
}

// ---------------------------------------------------------------------------
extern "C" void kernel_launch(void* const* d_in, const int* in_sizes, int n_in,
                              void* d_out, int out_size)
{
  const int*   c_ids   = (const int*)d_in[0];
  const int*   pos_ids = (const int*)d_in[1];
  const int*   neg_ids = (const int*)d_in[2];
  const int*   n00 = (const int*)d_in[3];
  const int*   n01 = (const int*)d_in[4];
  const int*   n02 = (const int*)d_in[5];
  const int*   n10 = (const int*)d_in[6];
  const int*   n11 = (const int*)d_in[7];
  const int*   n12 = (const int*)d_in[8];
  // d_in[9..11] = neigh_s2_* (unused)
  const float* emb0 = (const float*)d_in[12];
  const float* emb1 = (const float*)d_in[13];
  const float* emb2 = (const float*)d_in[14];
  const float* Wih  = (const float*)d_in[15];
  const float* Whh  = (const float*)d_in[16];
  const float* bih  = (const float*)d_in[17];
  const float* bhh  = (const float*)d_in[18];
  const float* attW = (const float*)d_in[19];

  cudaFuncSetAttribute(precompute_P_kernel, cudaFuncAttributeMaxDynamicSharedMemorySize, P_SMEM_BYTES);
  cudaFuncSetAttribute(rnn_mma_kernel,      cudaFuncAttributeMaxDynamicSharedMemorySize, RNN_SMEM_BYTES);

  precompute_P_kernel<<<dim3(157, 6), 512, P_SMEM_BYTES>>>(emb0, emb1, emb2, Wih, bih, bhh);
  rnn_mma_kernel<<<dim3(48, 6), 512, RNN_SMEM_BYTES>>>(Whh, c_ids,
                                                       n00, n01, n02, n10, n11, n12);
  attn_kernel<<<dim3(BSZ + T1PAD), 128>>>(emb0, emb1, c_ids, attW, (float*)d_out);
  scatter_kernel<<<dim3(BSZ, 2), 128>>>(pos_ids, neg_ids, (float*)d_out);
}

// round 9
// speedup vs baseline: 5.7650x; 1.1325x over previous
#include <cuda_runtime.h>
#include <cstdint>

#define DV 128
#define NSTEP 10
#define BSZ 4096
#define CNT0 20000
#define CNT1 2000
#define CNT2 15000
#define ROWS_TOT (CNT0 + CNT1 + CNT2)
#define T1PAD 2048   // type-1 node count padded to tile multiple

typedef unsigned long long u64;

__device__ __align__(16) float g_P[2 * ROWS_TOT * DV];          // x@Wih^T + bih + bhh
__device__ __align__(16) float g_aggC[6 * BSZ * DV];            // c-set RNN means  [lay*3+nt][b]
__device__ __align__(16) float g_aggT[6 * T1PAD * DV];          // type-1 RNN means [lay*3+nt][node]
__device__ __align__(16) float g_attnT[T1PAD * DV];             // type-1 attention output per node

static __device__ __forceinline__ float tanh_fast(float x){
  float e = __expf(2.0f * x);
  return 1.0f - __fdividef(2.0f, e + 1.0f);
}
static __device__ __forceinline__ uint32_t tf32b(float v){
  uint32_t b;
  asm("cvt.rna.tf32.f32 %0, %1;" : "=r"(b) : "f"(v));
  return b;
}
// m16n8k8 tf32 HMMA: A row-major 16x8, B col-major 8x8 (k x n), C f32 16x8
static __device__ __forceinline__ void mma_tf32(float* c,
    uint32_t a0, uint32_t a1, uint32_t a2, uint32_t a3, uint32_t b0, uint32_t b1){
  asm volatile("mma.sync.aligned.m16n8k8.row.col.f32.tf32.tf32.f32 "
    "{%0,%1,%2,%3}, {%4,%5,%6,%7}, {%8,%9}, {%0,%1,%2,%3};"
    : "+f"(c[0]), "+f"(c[1]), "+f"(c[2]), "+f"(c[3])
    : "r"(a0), "r"(a1), "r"(a2), "r"(a3), "r"(b0), "r"(b1));
}

// ---------------------------------------------------------------------------
// Kernel 1 (fused): P[l][nt] = emb[nt] @ Wih[l,nt]^T + bih + bhh via HMMA.
// One block = 2 layers x 2 row-tiles. WF for BOTH layers resident; XB built
// once per row-tile, consumed by both layers' MMA; OT aliases XB.
// smem (floats): WF0 16384 | WF1 16384 | XB/OT 17408  -> 200,704 B
// grid.x flattened over row-tile-pairs: nt0 [0,79), nt1 [79,87), nt2 [87,146)
// ---------------------------------------------------------------------------
#define PXB 32768
#define P_SMEM_BYTES ((32768 + 17408) * 4)

__global__ void __launch_bounds__(512, 1) precompute_P_kernel(
    const float* __restrict__ emb0, const float* __restrict__ emb1, const float* __restrict__ emb2,
    const float* __restrict__ Wih, const float* __restrict__ bih, const float* __restrict__ bhh)
{
  extern __shared__ float smf[];
  float* XB = smf + PXB;
  float* OT = smf + PXB;      // alias (phases separated by syncs)

  const int tid  = threadIdx.x;
  const int w    = tid >> 5;
  const int lane = tid & 31;
  const int g    = lane >> 2;
  const int t    = lane & 3;

  int xb = blockIdx.x, nt, tile0, rows;
  if (xb < 79)      { nt = 0; tile0 = xb * 2;        rows = CNT0; }
  else if (xb < 87) { nt = 1; tile0 = (xb - 79) * 2; rows = CNT1; }
  else              { nt = 2; tile0 = (xb - 87) * 2; rows = CNT2; }
  const float* emb = (nt == 0) ? emb0 : ((nt == 1) ? emb1 : emb2);

  // W fragments for BOTH layers (tf32-rna)
  for (int idx = tid; idx < 8192; idx += 512){
    int ll  = idx & 31;
    int kc  = (idx >> 5) & 15;
    int jsb = (idx >> 9) & 7;
    int lay = idx >> 12;
    const float* Wb = Wih + (size_t)(lay * 3 + nt) * DV * DV;
    int gg = ll >> 2, tt = ll & 3;
    int j = 16 * jsb + gg, k = 8 * kc + tt;
    uint4 hi;
    hi.x = tf32b(Wb[j * DV + k]);
    hi.y = tf32b(Wb[(j + 8) * DV + k]);
    hi.z = tf32b(Wb[j * DV + k + 4]);
    hi.w = tf32b(Wb[(j + 8) * DV + k + 4]);
    *(uint4*)&smf[lay * 16384 + (jsb * 16 + kc) * 128 + ll * 4] = hi;
  }

  const int js = w & 7;
  const int j0 = js << 4;
  const int m0base = (w >> 3) << 6;

  #pragma unroll
  for (int sub = 0; sub < 2; sub++){
    const int row0 = (tile0 + sub) * 128;
    if (row0 >= rows) break;

    __syncthreads();   // prior STG reads of OT (aliased) done; WF build done (sub=0)

    // x tile into (k,k+4)-pair layout, tf32-rounded
    {
      uint32_t* XBu = (uint32_t*)XB;
      for (int idx = tid; idx < 4096; idx += 512){
        int m = idx >> 5, q = idx & 31;
        int gr = row0 + m;
        float4 v = make_float4(0.f, 0.f, 0.f, 0.f);
        if (gr < rows) v = *(const float4*)(emb + (size_t)gr * DV + 4 * q);
        const float* ve = (const float*)&v;
        #pragma unroll
        for (int e = 0; e < 4; e++){
          int k = 4 * q + e;
          XBu[((k >> 3) * 128 + m) * 8 + (k & 3) * 2 + ((k >> 2) & 1)] = tf32b(ve[e]);
        }
      }
    }
    __syncthreads();

    // both layers' MMA while XB is hot
    float c0[8][4], c1[8][4];
    #pragma unroll
    for (int mt = 0; mt < 8; mt++)
      #pragma unroll
      for (int q = 0; q < 4; q++){ c0[mt][q] = 0.0f; c1[mt][q] = 0.0f; }

    #pragma unroll 2
    for (int kc = 0; kc < 16; kc++){
      uint4 A0 = *(const uint4*)&smf[(js * 16 + kc) * 128 + lane * 4];
      uint4 A1 = *(const uint4*)&smf[16384 + (js * 16 + kc) * 128 + lane * 4];
      #pragma unroll
      for (int mt = 0; mt < 8; mt++){
        float2 b = *(const float2*)&XB[(kc * 128 + m0base + 8 * mt + g) * 8 + t * 2];
        uint32_t b0 = __float_as_uint(b.x), b1 = __float_as_uint(b.y);
        mma_tf32(c0[mt], A0.x, A0.y, A0.z, A0.w, b0, b1);
        mma_tf32(c1[mt], A1.x, A1.y, A1.z, A1.w, b0, b1);
      }
    }
    __syncthreads();   // XB reads complete before OT overwrite

    #pragma unroll
    for (int lay = 0; lay < 2; lay++){
      const int comb = lay * 3 + nt;
      const float bj0 = bih[(size_t)comb * DV + j0 + g]     + bhh[(size_t)comb * DV + j0 + g];
      const float bj8 = bih[(size_t)comb * DV + j0 + g + 8] + bhh[(size_t)comb * DV + j0 + g + 8];
      float (*c)[4] = lay ? c1 : c0;
      #pragma unroll
      for (int mt = 0; mt < 8; mt++){
        int m0 = m0base + 8 * mt;
        OT[(m0 + 2 * t    ) * 136 + j0 + g    ] = c[mt][0] + bj0;
        OT[(m0 + 2 * t + 1) * 136 + j0 + g    ] = c[mt][1] + bj0;
        OT[(m0 + 2 * t    ) * 136 + j0 + g + 8] = c[mt][2] + bj8;
        OT[(m0 + 2 * t + 1) * 136 + j0 + g + 8] = c[mt][3] + bj8;
      }
      __syncthreads();
      const size_t Poff = (size_t)lay * ROWS_TOT * DV
                        + (size_t)((nt == 0) ? 0 : ((nt == 1) ? CNT0 : (CNT0 + CNT1))) * DV;
      for (int idx = tid; idx < 4096; idx += 512){
        int m = idx >> 5, q = idx & 31;
        int gr = row0 + m;
        if (gr < rows)
          *(float4*)(g_P + Poff + (size_t)gr * DV + 4 * q) = *(const float4*)&OT[m * 136 + 4 * q];
      }
      if (lay == 0) __syncthreads();   // l0 STG reads done before l1 OT write
    }
  }
}

// ---------------------------------------------------------------------------
// Kernel 2: RNN via mma.sync tf32 (deduped; unchanged from R8 win).
// ---------------------------------------------------------------------------
#define WF_F 0
#define HP_F 16384
#define NID_F 49152
#define RNN_SMEM_BYTES ((49152 + 1280) * 4)

__global__ void __launch_bounds__(512, 1) rnn_mma_kernel(
    const float* __restrict__ Whh,
    const int* __restrict__ c_ids,
    const int* __restrict__ n00, const int* __restrict__ n01, const int* __restrict__ n02,
    const int* __restrict__ n10, const int* __restrict__ n11, const int* __restrict__ n12)
{
  extern __shared__ float smf[];
  float* WF = smf + WF_F;
  float* HP = smf + HP_F;
  int* nidsh = (int*)(smf + NID_F);

  const int tid  = threadIdx.x;
  const int w    = tid >> 5;
  const int lane = tid & 31;
  const int g    = lane >> 2;
  const int t    = lane & 3;

  const int y   = blockIdx.y;       // lay*3 + nt
  const int lay = y / 3;
  const int nt  = y % 3;
  const int xb  = blockIdx.x;
  const bool isT = (xb >= 32);
  const int ntype = isT ? 1 : 0;
  const int row0  = (isT ? (xb - 32) : xb) * 128;
  const int nsel = ntype * 3 + nt;
  const int* ntab = (nsel == 0) ? n00 : (nsel == 1) ? n01 : (nsel == 2) ? n02
                  : (nsel == 3) ? n10 : (nsel == 4) ? n11 : n12;
  const float* Wb = Whh + (size_t)(lay * 3 + nt) * DV * DV;
  const float* Pb = g_P + (size_t)lay * ROWS_TOT * DV
                  + (size_t)((nt == 0) ? 0 : ((nt == 1) ? CNT0 : (CNT0 + CNT1))) * DV;

  for (int idx = tid; idx < 4096; idx += 512){
    int ll  = idx & 31;
    int kc  = (idx >> 5) & 15;
    int jsb = idx >> 9;
    int gg = ll >> 2, tt = ll & 3;
    int j = 16 * jsb + gg, k = 8 * kc + tt;
    uint4 hi;
    hi.x = tf32b(Wb[j * DV + k]);
    hi.y = tf32b(Wb[(j + 8) * DV + k]);
    hi.z = tf32b(Wb[j * DV + k + 4]);
    hi.w = tf32b(Wb[(j + 8) * DV + k + 4]);
    *(uint4*)&WF[(jsb * 16 + kc) * 128 + ll * 4] = hi;
  }
  for (int idx = tid; idx < 128 * NSTEP; idx += 512){
    int r = idx / NSTEP, s = idx % NSTEP;
    int id = isT ? min(row0 + r, CNT1 - 1) : c_ids[row0 + r];
    nidsh[idx] = ntab[(size_t)id * NSTEP + s];
  }
  __syncthreads();

  const int js = w & 7;
  const int j0 = js << 4;
  const int m0base = (w >> 3) << 6;

  float hsum[8][4];
  #pragma unroll
  for (int mt = 0; mt < 8; mt++)
    #pragma unroll
    for (int q = 0; q < 4; q++) hsum[mt][q] = 0.0f;

  float pf[4][4], pf2[4][4];

  for (int s = 0; s < NSTEP; s++){
    float* HPr = HP + (((s + 1) & 1) << 14);
    float* HPw = HP + ((s & 1) << 14);

    #pragma unroll
    for (int mt = 0; mt < 4; mt++){
      int m0 = m0base + 8 * mt;
      int nv0 = nidsh[(m0 + 2 * t) * NSTEP + s];
      int nv1 = nidsh[(m0 + 2 * t + 1) * NSTEP + s];
      const float* P0 = Pb + (size_t)nv0 * DV;
      const float* P1 = Pb + (size_t)nv1 * DV;
      pf[mt][0] = P0[j0 + g];     pf[mt][1] = P1[j0 + g];
      pf[mt][2] = P0[j0 + g + 8]; pf[mt][3] = P1[j0 + g + 8];
    }

    float c[8][4];
    #pragma unroll
    for (int mt = 0; mt < 8; mt++)
      #pragma unroll
      for (int q = 0; q < 4; q++) c[mt][q] = 0.0f;

    if (s > 0){
      #pragma unroll 2
      for (int kc = 0; kc < 16; kc++){
        uint4 A = *(const uint4*)&WF[(js * 16 + kc) * 128 + lane * 4];
        #pragma unroll
        for (int mt = 0; mt < 8; mt++){
          float2 b = *(const float2*)&HPr[(kc * 128 + m0base + 8 * mt + g) * 8 + t * 2];
          mma_tf32(c[mt], A.x, A.y, A.z, A.w,
                   __float_as_uint(b.x), __float_as_uint(b.y));
        }
      }
    }

    #pragma unroll
    for (int mt = 0; mt < 4; mt++){
      int m0 = m0base + 8 * (mt + 4);
      int nv0 = nidsh[(m0 + 2 * t) * NSTEP + s];
      int nv1 = nidsh[(m0 + 2 * t + 1) * NSTEP + s];
      const float* P0 = Pb + (size_t)nv0 * DV;
      const float* P1 = Pb + (size_t)nv1 * DV;
      pf2[mt][0] = P0[j0 + g];     pf2[mt][1] = P1[j0 + g];
      pf2[mt][2] = P0[j0 + g + 8]; pf2[mt][3] = P1[j0 + g + 8];
    }

    #pragma unroll
    for (int mt = 0; mt < 8; mt++){
      const float* pp = (mt < 4) ? pf[mt] : pf2[mt - 4];
      int m0 = m0base + 8 * mt;
      float v0 = tanh_fast(c[mt][0] + pp[0]);
      float v1 = tanh_fast(c[mt][1] + pp[1]);
      float v2 = tanh_fast(c[mt][2] + pp[2]);
      float v3 = tanh_fast(c[mt][3] + pp[3]);
      hsum[mt][0] += v0; hsum[mt][1] += v1; hsum[mt][2] += v2; hsum[mt][3] += v3;
      int pi = (g < 4) ? g : (g - 4);
      int comp = (g < 4) ? 0 : 1;
      int kcA = j0 >> 3, kcB = kcA + 1;
      uint32_t* HPu = (uint32_t*)HPw;
      HPu[(kcA * 128 + m0 + 2 * t    ) * 8 + pi * 2 + comp] = tf32b(v0);
      HPu[(kcA * 128 + m0 + 2 * t + 1) * 8 + pi * 2 + comp] = tf32b(v1);
      HPu[(kcB * 128 + m0 + 2 * t    ) * 8 + pi * 2 + comp] = tf32b(v2);
      HPu[(kcB * 128 + m0 + 2 * t + 1) * 8 + pi * 2 + comp] = tf32b(v3);
    }
    __syncthreads();
  }

  float* HT = HP;
  const float inv = 1.0f / NSTEP;
  #pragma unroll
  for (int mt = 0; mt < 8; mt++){
    int m0 = m0base + 8 * mt;
    HT[(m0 + 2 * t    ) * 128 + j0 + g    ] = hsum[mt][0] * inv;
    HT[(m0 + 2 * t + 1) * 128 + j0 + g    ] = hsum[mt][1] * inv;
    HT[(m0 + 2 * t    ) * 128 + j0 + g + 8] = hsum[mt][2] * inv;
    HT[(m0 + 2 * t + 1) * 128 + j0 + g + 8] = hsum[mt][3] * inv;
  }
  __syncthreads();
  float* ob = isT ? (g_aggT + ((size_t)y * T1PAD + row0) * DV)
                  : (g_aggC + ((size_t)y * BSZ  + row0) * DV);
  float4* ob4 = (float4*)ob;
  const float4* hp4 = (const float4*)HT;
  for (int idx = tid; idx < 4096; idx += 512) ob4[idx] = hp4[idx];
}

// ---------------------------------------------------------------------------
// Kernel 3: attention (deduped; unchanged from R8 win).
// ---------------------------------------------------------------------------
static __device__ __forceinline__ float breduce128(float v, float* sh){
  #pragma unroll
  for (int o = 16; o > 0; o >>= 1) v += __shfl_xor_sync(0xffffffffu, v, o);
  if ((threadIdx.x & 31) == 0) sh[threadIdx.x >> 5] = v;
  __syncthreads();
  float r = sh[0] + sh[1] + sh[2] + sh[3];
  __syncthreads();
  return r;
}

__global__ void __launch_bounds__(128) attn_kernel(
    const float* __restrict__ emb0, const float* __restrict__ emb1,
    const int* __restrict__ c_ids,
    const float* __restrict__ attW, float* __restrict__ out)
{
  __shared__ float sh[4];
  const int b  = blockIdx.x;
  const int d  = threadIdx.x;
  const bool isT = (b >= BSZ);
  const int node = b - BSZ;
  if (isT && node >= CNT1) return;
  const int ntype = isT ? 1 : 0;
  const float* agg = isT ? g_aggT : g_aggC;
  const int nrows  = isT ? T1PAD : BSZ;
  const int ridx   = isT ? node : b;
  float cur = isT ? emb1[(size_t)node * DV + d] : emb0[(size_t)c_ids[b] * DV + d];

  #pragma unroll
  for (int l = 0; l < 2; l++){
    const float* aw = attW + (size_t)(l * 3 + ntype) * 2 * DV;
    float awc = aw[d];
    float awn = aw[DV + d];
    float st0 = agg[((size_t)(l * 3 + 0) * nrows + ridx) * DV + d];
    float st1 = agg[((size_t)(l * 3 + 1) * nrows + ridx) * DV + d];
    float st2 = agg[((size_t)(l * 3 + 2) * nrows + ridx) * DV + d];
    float base = breduce128(cur * awc, sh);
    float s0 = base + breduce128(cur * awn, sh);
    float s1 = base + breduce128(st0 * awn, sh);
    float s2 = base + breduce128(st1 * awn, sh);
    float s3 = base + breduce128(st2 * awn, sh);
    float m = fmaxf(fmaxf(s0, s1), fmaxf(s2, s3));
    float e0 = expf(s0 - m), e1 = expf(s1 - m), e2 = expf(s2 - m), e3 = expf(s3 - m);
    float inv = 1.0f / (e0 + e1 + e2 + e3);
    float v = (e0 * cur + e1 * st0 + e2 * st1 + e3 * st2) * inv;
    cur = (v > 0.0f) ? v : 0.01f * v;
  }
  if (isT) g_attnT[(size_t)node * DV + d] = cur;
  else     out[(size_t)b * DV + d] = cur;
}

// Kernel 4: gather type-1 attention outputs by pos/neg ids (float4, 1 elt/thread).
__global__ void __launch_bounds__(256) scatter_kernel(
    const int* __restrict__ pos_ids, const int* __restrict__ neg_ids,
    float* __restrict__ out)
{
  const int i   = blockIdx.x * 256 + threadIdx.x;   // 262,144 total = exact cover
  const int q   = i & 31;
  const int b   = (i >> 5) & 4095;
  const int set = i >> 17;                          // 0 -> pos, 1 -> neg
  const int id  = set ? neg_ids[b] : pos_ids[b];
  ((float4*)out)[((size_t)(set + 1) * BSZ + b) * 32 + q] =
      ((const float4*)g_attnT)[(size_t)id * 32 + q];
}

// ---------------------------------------------------------------------------
extern "C" void kernel_launch(void* const* d_in, const int* in_sizes, int n_in,
                              void* d_out, int out_size)
{
  const int*   c_ids   = (const int*)d_in[0];
  const int*   pos_ids = (const int*)d_in[1];
  const int*   neg_ids = (const int*)d_in[2];
  const int*   n00 = (const int*)d_in[3];
  const int*   n01 = (const int*)d_in[4];
  const int*   n02 = (const int*)d_in[5];
  const int*   n10 = (const int*)d_in[6];
  const int*   n11 = (const int*)d_in[7];
  const int*   n12 = (const int*)d_in[8];
  // d_in[9..11] = neigh_s2_* (unused)
  const float* emb0 = (const float*)d_in[12];
  const float* emb1 = (const float*)d_in[13];
  const float* emb2 = (const float*)d_in[14];
  const float* Wih  = (const float*)d_in[15];
  const float* Whh  = (const float*)d_in[16];
  const float* bih  = (const float*)d_in[17];
  const float* bhh  = (const float*)d_in[18];
  const float* attW = (const float*)d_in[19];

  cudaFuncSetAttribute(precompute_P_kernel, cudaFuncAttributeMaxDynamicSharedMemorySize, P_SMEM_BYTES);
  cudaFuncSetAttribute(rnn_mma_kernel,      cudaFuncAttributeMaxDynamicSharedMemorySize, RNN_SMEM_BYTES);

  precompute_P_kernel<<<dim3(146), 512, P_SMEM_BYTES>>>(emb0, emb1, emb2, Wih, bih, bhh);
  rnn_mma_kernel<<<dim3(48, 6), 512, RNN_SMEM_BYTES>>>(Whh, c_ids,
                                                       n00, n01, n02, n10, n11, n12);
  attn_kernel<<<dim3(BSZ + T1PAD), 128>>>(emb0, emb1, c_ids, attW, (float*)d_out);
  scatter_kernel<<<dim3(1024), 256>>>(pos_ids, neg_ids, (float*)d_out);
}

// round 11
// speedup vs baseline: 7.0824x; 1.2285x over previous
#include <cuda_runtime.h>
#include <cuda_fp16.h>
#include <cstdint>

#define DV 128
#define NSTEP 10
#define BSZ 4096
#define CNT0 20000
#define CNT1 2000
#define CNT2 15000
#define ROWS_TOT (CNT0 + CNT1 + CNT2)
#define T1PAD 2048   // type-1 node count padded to tile multiple

typedef unsigned long long u64;

__device__ __align__(16) float g_P[2 * ROWS_TOT * DV];          // x@Wih^T + bih + bhh
__device__ __align__(16) float g_aggC[6 * BSZ * DV];            // c-set RNN means  [lay*3+nt][b]
__device__ __align__(16) float g_aggT[6 * T1PAD * DV];          // type-1 RNN means [lay*3+nt][node]
__device__ __align__(16) float g_attnT[T1PAD * DV];             // type-1 attention output per node

static __device__ __forceinline__ float tanh_fast(float x){
  float e = __expf(2.0f * x);
  return 1.0f - __fdividef(2.0f, e + 1.0f);
}
static __device__ __forceinline__ uint32_t tf32b(float v){
  uint32_t b;
  asm("cvt.rna.tf32.f32 %0, %1;" : "=r"(b) : "f"(v));
  return b;
}
static __device__ __forceinline__ uint32_t h2pack(float a, float b){
  __half2 h = __floats2half2_rn(a, b);
  return *(uint32_t*)&h;
}
// m16n8k8 tf32 HMMA (precompute kernel)
static __device__ __forceinline__ void mma_tf32(float* c,
    uint32_t a0, uint32_t a1, uint32_t a2, uint32_t a3, uint32_t b0, uint32_t b1){
  asm volatile("mma.sync.aligned.m16n8k8.row.col.f32.tf32.tf32.f32 "
    "{%0,%1,%2,%3}, {%4,%5,%6,%7}, {%8,%9}, {%0,%1,%2,%3};"
    : "+f"(c[0]), "+f"(c[1]), "+f"(c[2]), "+f"(c[3])
    : "r"(a0), "r"(a1), "r"(a2), "r"(a3), "r"(b0), "r"(b1));
}
// m16n8k16 fp16 HMMA, f32 accumulate (rnn kernel): A 16x16 row, B 16x8 col
static __device__ __forceinline__ void mma_f16(float* c,
    uint32_t a0, uint32_t a1, uint32_t a2, uint32_t a3, uint32_t b0, uint32_t b1){
  asm volatile("mma.sync.aligned.m16n8k16.row.col.f32.f16.f16.f32 "
    "{%0,%1,%2,%3}, {%4,%5,%6,%7}, {%8,%9}, {%0,%1,%2,%3};"
    : "+f"(c[0]), "+f"(c[1]), "+f"(c[2]), "+f"(c[3])
    : "r"(a0), "r"(a1), "r"(a2), "r"(a3), "r"(b0), "r"(b1));
}

// ---------------------------------------------------------------------------
// Kernel 1 (fused, unchanged from R9 win): P = emb @ Wih^T + biases, HMMA tf32.
// One block = 2 layers x 2 row-tiles.
// ---------------------------------------------------------------------------
#define PXB 32768
#define P_SMEM_BYTES ((32768 + 17408) * 4)

__global__ void __launch_bounds__(512, 1) precompute_P_kernel(
    const float* __restrict__ emb0, const float* __restrict__ emb1, const float* __restrict__ emb2,
    const float* __restrict__ Wih, const float* __restrict__ bih, const float* __restrict__ bhh)
{
  extern __shared__ float smf[];
  float* XB = smf + PXB;
  float* OT = smf + PXB;      // alias (phases separated by syncs)

  const int tid  = threadIdx.x;
  const int w    = tid >> 5;
  const int lane = tid & 31;
  const int g    = lane >> 2;
  const int t    = lane & 3;

  int xb = blockIdx.x, nt, tile0, rows;
  if (xb < 79)      { nt = 0; tile0 = xb * 2;        rows = CNT0; }
  else if (xb < 87) { nt = 1; tile0 = (xb - 79) * 2; rows = CNT1; }
  else              { nt = 2; tile0 = (xb - 87) * 2; rows = CNT2; }
  const float* emb = (nt == 0) ? emb0 : ((nt == 1) ? emb1 : emb2);

  for (int idx = tid; idx < 8192; idx += 512){
    int ll  = idx & 31;
    int kc  = (idx >> 5) & 15;
    int jsb = (idx >> 9) & 7;
    int lay = idx >> 12;
    const float* Wb = Wih + (size_t)(lay * 3 + nt) * DV * DV;
    int gg = ll >> 2, tt = ll & 3;
    int j = 16 * jsb + gg, k = 8 * kc + tt;
    uint4 hi;
    hi.x = tf32b(Wb[j * DV + k]);
    hi.y = tf32b(Wb[(j + 8) * DV + k]);
    hi.z = tf32b(Wb[j * DV + k + 4]);
    hi.w = tf32b(Wb[(j + 8) * DV + k + 4]);
    *(uint4*)&smf[lay * 16384 + (jsb * 16 + kc) * 128 + ll * 4] = hi;
  }

  const int js = w & 7;
  const int j0 = js << 4;
  const int m0base = (w >> 3) << 6;

  #pragma unroll
  for (int sub = 0; sub < 2; sub++){
    const int row0 = (tile0 + sub) * 128;
    if (row0 >= rows) break;

    __syncthreads();

    {
      uint32_t* XBu = (uint32_t*)XB;
      for (int idx = tid; idx < 4096; idx += 512){
        int m = idx >> 5, q = idx & 31;
        int gr = row0 + m;
        float4 v = make_float4(0.f, 0.f, 0.f, 0.f);
        if (gr < rows) v = *(const float4*)(emb + (size_t)gr * DV + 4 * q);
        const float* ve = (const float*)&v;
        #pragma unroll
        for (int e = 0; e < 4; e++){
          int k = 4 * q + e;
          XBu[((k >> 3) * 128 + m) * 8 + (k & 3) * 2 + ((k >> 2) & 1)] = tf32b(ve[e]);
        }
      }
    }
    __syncthreads();

    float c0[8][4], c1[8][4];
    #pragma unroll
    for (int mt = 0; mt < 8; mt++)
      #pragma unroll
      for (int q = 0; q < 4; q++){ c0[mt][q] = 0.0f; c1[mt][q] = 0.0f; }

    #pragma unroll 2
    for (int kc = 0; kc < 16; kc++){
      uint4 A0 = *(const uint4*)&smf[(js * 16 + kc) * 128 + lane * 4];
      uint4 A1 = *(const uint4*)&smf[16384 + (js * 16 + kc) * 128 + lane * 4];
      #pragma unroll
      for (int mt = 0; mt < 8; mt++){
        float2 b = *(const float2*)&XB[(kc * 128 + m0base + 8 * mt + g) * 8 + t * 2];
        uint32_t b0 = __float_as_uint(b.x), b1 = __float_as_uint(b.y);
        mma_tf32(c0[mt], A0.x, A0.y, A0.z, A0.w, b0, b1);
        mma_tf32(c1[mt], A1.x, A1.y, A1.z, A1.w, b0, b1);
      }
    }
    __syncthreads();

    #pragma unroll
    for (int lay = 0; lay < 2; lay++){
      const int comb = lay * 3 + nt;
      const float bj0 = bih[(size_t)comb * DV + j0 + g]     + bhh[(size_t)comb * DV + j0 + g];
      const float bj8 = bih[(size_t)comb * DV + j0 + g + 8] + bhh[(size_t)comb * DV + j0 + g + 8];
      float (*c)[4] = lay ? c1 : c0;
      #pragma unroll
      for (int mt = 0; mt < 8; mt++){
        int m0 = m0base + 8 * mt;
        OT[(m0 + 2 * t    ) * 136 + j0 + g    ] = c[mt][0] + bj0;
        OT[(m0 + 2 * t + 1) * 136 + j0 + g    ] = c[mt][1] + bj0;
        OT[(m0 + 2 * t    ) * 136 + j0 + g + 8] = c[mt][2] + bj8;
        OT[(m0 + 2 * t + 1) * 136 + j0 + g + 8] = c[mt][3] + bj8;
      }
      __syncthreads();
      const size_t Poff = (size_t)lay * ROWS_TOT * DV
                        + (size_t)((nt == 0) ? 0 : ((nt == 1) ? CNT0 : (CNT0 + CNT1))) * DV;
      for (int idx = tid; idx < 4096; idx += 512){
        int m = idx >> 5, q = idx & 31;
        int gr = row0 + m;
        if (gr < rows)
          *(float4*)(g_P + Poff + (size_t)gr * DV + 4 * q) = *(const float4*)&OT[m * 136 + 4 * q];
      }
      if (lay == 0) __syncthreads();
    }
  }
}

// ---------------------------------------------------------------------------
// Kernel 2: RNN via fp16 m16n8k16 HMMA. Two independent 256-thread groups
// (m-halves) with named barriers per step; loop-phase HP accesses are strictly
// row-partitioned (drift-safe). Block-wide syncs ONLY around the final
// mean-transpose, whose float-layout alias spans both groups' HP bytes
// (this was the R10 race).
// smem: WF 32KB | HP 2x32KB | nids 5KB = 103,424 B
// ---------------------------------------------------------------------------
#define RHP_F 8192                       // float offset of HP
#define RNID_F 24576
#define RNN_SMEM_BYTES ((24576 + 1280) * 4)

__global__ void __launch_bounds__(512, 1) rnn_mma_kernel(
    const float* __restrict__ Whh,
    const int* __restrict__ c_ids,
    const int* __restrict__ n00, const int* __restrict__ n01, const int* __restrict__ n02,
    const int* __restrict__ n10, const int* __restrict__ n11, const int* __restrict__ n12)
{
  extern __shared__ float smf[];
  uint4* WF4 = (uint4*)smf;                    // fp16 A fragments
  char*  HPc = (char*)(smf + RHP_F);           // 2 x 32KB fp16 h buffers
  int* nidsh = (int*)(smf + RNID_F);

  const int tid  = threadIdx.x;
  const int w    = tid >> 5;
  const int lane = tid & 31;
  const int g    = lane >> 2;
  const int t    = lane & 3;

  const int y   = blockIdx.y;       // lay*3 + nt
  const int lay = y / 3;
  const int nt  = y % 3;
  const int xb  = blockIdx.x;
  const bool isT = (xb >= 32);
  const int ntype = isT ? 1 : 0;
  const int row0  = (isT ? (xb - 32) : xb) * 128;
  const int nsel = ntype * 3 + nt;
  const int* ntab = (nsel == 0) ? n00 : (nsel == 1) ? n01 : (nsel == 2) ? n02
                  : (nsel == 3) ? n10 : (nsel == 4) ? n11 : n12;
  const float* Wb = Whh + (size_t)(lay * 3 + nt) * DV * DV;
  const float* Pb = g_P + (size_t)lay * ROWS_TOT * DV
                  + (size_t)((nt == 0) ? 0 : ((nt == 1) ? CNT0 : (CNT0 + CNT1))) * DV;

  // fp16 W fragments: entry = (jsb, kc, lane) -> a0..a3 (8 fp16 = 16x16 tile slice)
  for (int idx = tid; idx < 2048; idx += 512){
    int ll  = idx & 31;
    int kc  = (idx >> 5) & 7;
    int jsb = idx >> 8;
    int gg = ll >> 2, tt = ll & 3;
    int j = 16 * jsb + gg, k = 16 * kc + 2 * tt;
    uint4 A;
    A.x = h2pack(Wb[j * DV + k],           Wb[j * DV + k + 1]);
    A.y = h2pack(Wb[(j + 8) * DV + k],     Wb[(j + 8) * DV + k + 1]);
    A.z = h2pack(Wb[j * DV + k + 8],       Wb[j * DV + k + 9]);
    A.w = h2pack(Wb[(j + 8) * DV + k + 8], Wb[(j + 8) * DV + k + 9]);
    WF4[(jsb * 8 + kc) * 32 + ll] = A;
  }
  for (int idx = tid; idx < 128 * NSTEP; idx += 512){
    int r = idx / NSTEP, s = idx % NSTEP;
    int id = isT ? min(row0 + r, CNT1 - 1) : c_ids[row0 + r];
    nidsh[idx] = ntab[(size_t)id * NSTEP + s];
  }
  __syncthreads();   // groups independent during the recurrence loop

  const int js = w & 7;
  const int j0 = js << 4;
  const int m0base = (w >> 3) << 6;   // group 0: m 0-63, group 1: m 64-127
  const int barid = 1 + (w >> 3);

  float hsum[8][4];
  #pragma unroll
  for (int mt = 0; mt < 8; mt++)
    #pragma unroll
    for (int q = 0; q < 4; q++) hsum[mt][q] = 0.0f;

  float pf[4][4], pf2[4][4];

  for (int s = 0; s < NSTEP; s++){
    char* HPr = HPc + (((s + 1) & 1) << 15);
    char* HPw = HPc + ((s & 1) << 15);

    #pragma unroll
    for (int mt = 0; mt < 4; mt++){
      int m0 = m0base + 8 * mt;
      int nv0 = nidsh[(m0 + 2 * t) * NSTEP + s];
      int nv1 = nidsh[(m0 + 2 * t + 1) * NSTEP + s];
      const float* P0 = Pb + (size_t)nv0 * DV;
      const float* P1 = Pb + (size_t)nv1 * DV;
      pf[mt][0] = P0[j0 + g];     pf[mt][1] = P1[j0 + g];
      pf[mt][2] = P0[j0 + g + 8]; pf[mt][3] = P1[j0 + g + 8];
    }

    float c[8][4];
    #pragma unroll
    for (int mt = 0; mt < 8; mt++)
      #pragma unroll
      for (int q = 0; q < 4; q++) c[mt][q] = 0.0f;

    if (s > 0){
      #pragma unroll
      for (int kc = 0; kc < 8; kc++){
        uint4 A = WF4[(js * 8 + kc) * 32 + lane];
        #pragma unroll
        for (int mt = 0; mt < 8; mt++){
          uint2 b = *(const uint2*)(HPr + ((size_t)((kc * 128 + m0base + 8 * mt + g) * 4 + t) << 3));
          mma_f16(c[mt], A.x, A.y, A.z, A.w, b.x, b.y);
        }
      }
    }

    #pragma unroll
    for (int mt = 0; mt < 4; mt++){
      int m0 = m0base + 8 * (mt + 4);
      int nv0 = nidsh[(m0 + 2 * t) * NSTEP + s];
      int nv1 = nidsh[(m0 + 2 * t + 1) * NSTEP + s];
      const float* P0 = Pb + (size_t)nv0 * DV;
      const float* P1 = Pb + (size_t)nv1 * DV;
      pf2[mt][0] = P0[j0 + g];     pf2[mt][1] = P1[j0 + g];
      pf2[mt][2] = P0[j0 + g + 8]; pf2[mt][3] = P1[j0 + g + 8];
    }

    __half* HW = (__half*)HPw;
    #pragma unroll
    for (int mt = 0; mt < 8; mt++){
      const float* pp = (mt < 4) ? pf[mt] : pf2[mt - 4];
      int m0 = m0base + 8 * mt;
      float v0 = tanh_fast(c[mt][0] + pp[0]);   // (j0+g,   m0+2t)
      float v1 = tanh_fast(c[mt][1] + pp[1]);   // (j0+g,   m0+2t+1)
      float v2 = tanh_fast(c[mt][2] + pp[2]);   // (j0+g+8, m0+2t)
      float v3 = tanh_fast(c[mt][3] + pp[3]);   // (j0+g+8, m0+2t+1)
      hsum[mt][0] += v0; hsum[mt][1] += v1; hsum[mt][2] += v2; hsum[mt][3] += v3;
      // h -> fp16 pair layout: kc'=js; halves [4t..4t+3] of row = k {2t,2t+1,2t+8,2t+9}
      int i0 = js * 2048 + (m0 + 2 * t) * 16 + (g >> 1) * 4 + (g & 1);
      HW[i0]      = __float2half_rn(v0);
      HW[i0 + 2]  = __float2half_rn(v2);
      HW[i0 + 16] = __float2half_rn(v1);
      HW[i0 + 18] = __float2half_rn(v3);
    }
    asm volatile("bar.sync %0, %1;" :: "r"(barid), "r"(256) : "memory");
  }

  // FIX (R10 race): the HT float alias below spans BOTH groups' HP bytes, so
  // drain every group's HP reads with a block-wide sync before overwriting.
  __syncthreads();

  float* HT = smf + RHP_F;   // 64KB float scratch over both HP buffers
  const float inv = 1.0f / NSTEP;
  #pragma unroll
  for (int mt = 0; mt < 8; mt++){
    int m0 = m0base + 8 * mt;
    HT[(m0 + 2 * t    ) * 128 + j0 + g    ] = hsum[mt][0] * inv;
    HT[(m0 + 2 * t + 1) * 128 + j0 + g    ] = hsum[mt][1] * inv;
    HT[(m0 + 2 * t    ) * 128 + j0 + g + 8] = hsum[mt][2] * inv;
    HT[(m0 + 2 * t + 1) * 128 + j0 + g + 8] = hsum[mt][3] * inv;
  }
  __syncthreads();
  float* ob = isT ? (g_aggT + ((size_t)y * T1PAD + row0) * DV)
                  : (g_aggC + ((size_t)y * BSZ  + row0) * DV);
  for (int idx = tid; idx < 4096; idx += 512){
    int m = idx >> 5;
    int q = idx & 31;
    ((float4*)ob)[m * 32 + q] = *(const float4*)&HT[m * 128 + 4 * q];
  }
}

// ---------------------------------------------------------------------------
// Kernel 3: attention (deduped; unchanged).
// ---------------------------------------------------------------------------
static __device__ __forceinline__ float breduce128(float v, float* sh){
  #pragma unroll
  for (int o = 16; o > 0; o >>= 1) v += __shfl_xor_sync(0xffffffffu, v, o);
  if ((threadIdx.x & 31) == 0) sh[threadIdx.x >> 5] = v;
  __syncthreads();
  float r = sh[0] + sh[1] + sh[2] + sh[3];
  __syncthreads();
  return r;
}

__global__ void __launch_bounds__(128) attn_kernel(
    const float* __restrict__ emb0, const float* __restrict__ emb1,
    const int* __restrict__ c_ids,
    const float* __restrict__ attW, float* __restrict__ out)
{
  __shared__ float sh[4];
  const int b  = blockIdx.x;
  const int d  = threadIdx.x;
  const bool isT = (b >= BSZ);
  const int node = b - BSZ;
  if (isT && node >= CNT1) return;
  const int ntype = isT ? 1 : 0;
  const float* agg = isT ? g_aggT : g_aggC;
  const int nrows  = isT ? T1PAD : BSZ;
  const int ridx   = isT ? node : b;
  float cur = isT ? emb1[(size_t)node * DV + d] : emb0[(size_t)c_ids[b] * DV + d];

  #pragma unroll
  for (int l = 0; l < 2; l++){
    const float* aw = attW + (size_t)(l * 3 + ntype) * 2 * DV;
    float awc = aw[d];
    float awn = aw[DV + d];
    float st0 = agg[((size_t)(l * 3 + 0) * nrows + ridx) * DV + d];
    float st1 = agg[((size_t)(l * 3 + 1) * nrows + ridx) * DV + d];
    float st2 = agg[((size_t)(l * 3 + 2) * nrows + ridx) * DV + d];
    float base = breduce128(cur * awc, sh);
    float s0 = base + breduce128(cur * awn, sh);
    float s1 = base + breduce128(st0 * awn, sh);
    float s2 = base + breduce128(st1 * awn, sh);
    float s3 = base + breduce128(st2 * awn, sh);
    float m = fmaxf(fmaxf(s0, s1), fmaxf(s2, s3));
    float e0 = expf(s0 - m), e1 = expf(s1 - m), e2 = expf(s2 - m), e3 = expf(s3 - m);
    float inv = 1.0f / (e0 + e1 + e2 + e3);
    float v = (e0 * cur + e1 * st0 + e2 * st1 + e3 * st2) * inv;
    cur = (v > 0.0f) ? v : 0.01f * v;
  }
  if (isT) g_attnT[(size_t)node * DV + d] = cur;
  else     out[(size_t)b * DV + d] = cur;
}

// Kernel 4: gather type-1 attention outputs by pos/neg ids (float4/thread).
__global__ void __launch_bounds__(256) scatter_kernel(
    const int* __restrict__ pos_ids, const int* __restrict__ neg_ids,
    float* __restrict__ out)
{
  const int i   = blockIdx.x * 256 + threadIdx.x;   // 262,144 total = exact cover
  const int q   = i & 31;
  const int b   = (i >> 5) & 4095;
  const int set = i >> 17;                          // 0 -> pos, 1 -> neg
  const int id  = set ? neg_ids[b] : pos_ids[b];
  ((float4*)out)[((size_t)(set + 1) * BSZ + b) * 32 + q] =
      ((const float4*)g_attnT)[(size_t)id * 32 + q];
}

// ---------------------------------------------------------------------------
extern "C" void kernel_launch(void* const* d_in, const int* in_sizes, int n_in,
                              void* d_out, int out_size)
{
  const int*   c_ids   = (const int*)d_in[0];
  const int*   pos_ids = (const int*)d_in[1];
  const int*   neg_ids = (const int*)d_in[2];
  const int*   n00 = (const int*)d_in[3];
  const int*   n01 = (const int*)d_in[4];
  const int*   n02 = (const int*)d_in[5];
  const int*   n10 = (const int*)d_in[6];
  const int*   n11 = (const int*)d_in[7];
  const int*   n12 = (const int*)d_in[8];
  // d_in[9..11] = neigh_s2_* (unused)
  const float* emb0 = (const float*)d_in[12];
  const float* emb1 = (const float*)d_in[13];
  const float* emb2 = (const float*)d_in[14];
  const float* Wih  = (const float*)d_in[15];
  const float* Whh  = (const float*)d_in[16];
  const float* bih  = (const float*)d_in[17];
  const float* bhh  = (const float*)d_in[18];
  const float* attW = (const float*)d_in[19];

  cudaFuncSetAttribute(precompute_P_kernel, cudaFuncAttributeMaxDynamicSharedMemorySize, P_SMEM_BYTES);
  cudaFuncSetAttribute(rnn_mma_kernel,      cudaFuncAttributeMaxDynamicSharedMemorySize, RNN_SMEM_BYTES);

  precompute_P_kernel<<<dim3(146), 512, P_SMEM_BYTES>>>(emb0, emb1, emb2, Wih, bih, bhh);
  rnn_mma_kernel<<<dim3(48, 6), 512, RNN_SMEM_BYTES>>>(Whh, c_ids,
                                                       n00, n01, n02, n10, n11, n12);
  attn_kernel<<<dim3(BSZ + T1PAD), 128>>>(emb0, emb1, c_ids, attW, (float*)d_out);
  scatter_kernel<<<dim3(1024), 256>>>(pos_ids, neg_ids, (float*)d_out);
}